// round 4
// baseline (speedup 1.0000x reference)
#include <cuda_runtime.h>
#include <cuda_fp16.h>
#include <cstdint>

#define BATCH 8192
#define NFEAT 32
#define EDIM  64
#define VOCAB 1000
#define NPAIR 496
#define DIN   2544
#define K1P   2560
#define DH1   1024
#define DH2   512
#define DOUT  1000
#define N3P   1024

typedef __half f16;

// ---------------- scratch (device globals; no runtime allocation) ----------
__device__ f16 g_h0hi[(size_t)BATCH * K1P];
__device__ f16 g_h0lo[(size_t)BATCH * K1P];
__device__ f16 g_h1hi[(size_t)BATCH * DH1];
__device__ f16 g_h1lo[(size_t)BATCH * DH1];
__device__ f16 g_h2hi[(size_t)BATCH * DH2];
__device__ f16 g_h2lo[(size_t)BATCH * DH2];
__device__ f16 g_W1hi[(size_t)DH1 * K1P];
__device__ f16 g_W1lo[(size_t)DH1 * K1P];
__device__ f16 g_W2hi[(size_t)DH2 * DH1];
__device__ f16 g_W2lo[(size_t)DH2 * DH1];
__device__ f16 g_W3hi[(size_t)N3P * DH2];
__device__ f16 g_W3lo[(size_t)N3P * DH2];
__device__ int g_pairs[NPAIR];

// ---------------- helpers ---------------------------------------------------
__device__ __forceinline__ uint32_t smem_u32(const void* p) {
    return (uint32_t)__cvta_generic_to_shared(p);
}
__device__ __forceinline__ void cp_async16(uint32_t dst, const void* src) {
    asm volatile("cp.async.cg.shared.global [%0], [%1], 16;\n" :: "r"(dst), "l"(src));
}
__device__ __forceinline__ void split_f16(float v, f16& h, f16& l) {
    h = __float2half_rn(v);
    l = __float2half_rn(v - __half2float(h));
}
__device__ __forceinline__ void ldsm4(uint32_t addr, uint32_t& r0, uint32_t& r1,
                                      uint32_t& r2, uint32_t& r3) {
    asm volatile("ldmatrix.sync.aligned.m8n8.x4.shared.b16 {%0,%1,%2,%3}, [%4];\n"
                 : "=r"(r0), "=r"(r1), "=r"(r2), "=r"(r3) : "r"(addr));
}
__device__ __forceinline__ void mma_fp16(float c[4], const uint32_t a[4],
                                         uint32_t b0, uint32_t b1) {
    asm volatile("mma.sync.aligned.m16n8k16.row.col.f32.f16.f16.f32 "
                 "{%0,%1,%2,%3},{%4,%5,%6,%7},{%8,%9},{%0,%1,%2,%3};\n"
                 : "+f"(c[0]), "+f"(c[1]), "+f"(c[2]), "+f"(c[3])
                 : "r"(a[0]), "r"(a[1]), "r"(a[2]), "r"(a[3]), "r"(b0), "r"(b1));
}

// ---------------------------------------------------------------------------
// pair index table: p -> (i<<8)|j for upper-triangle row-major order
// ---------------------------------------------------------------------------
__global__ void init_pairs_kernel() {
    const int p = threadIdx.x;
    if (p < NPAIR) {
        int i = 0, s = 0;
        while (p >= s + (NFEAT - 1 - i)) { s += NFEAT - 1 - i; i++; }
        g_pairs[p] = (i << 8) | (i + 1 + (p - s));
    }
}

// ---------------------------------------------------------------------------
// Weight conversion: W[K][N] fp32 -> transposed hi/lo fp16 [Npad][Kpad], zero pad
// ---------------------------------------------------------------------------
__global__ void convert_w_kernel(const float* __restrict__ W,
                                 f16* __restrict__ hi, f16* __restrict__ lo,
                                 int K, int N, int Kpad, int Npad) {
    __shared__ float t[32][33];
    const int n0 = blockIdx.x * 32;
    const int k0 = blockIdx.y * 32;
    for (int r = threadIdx.y; r < 32; r += 8) {
        int k = k0 + r, n = n0 + threadIdx.x;
        t[r][threadIdx.x] = (k < K && n < N) ? W[(size_t)k * N + n] : 0.f;
    }
    __syncthreads();
    for (int r = threadIdx.y; r < 32; r += 8) {
        int n = n0 + r, k = k0 + threadIdx.x;
        if (n < Npad && k < Kpad) {
            float v = t[threadIdx.x][r];
            f16 h, l; split_f16(v, h, l);
            hi[(size_t)n * Kpad + k] = h;
            lo[(size_t)n * Kpad + k] = l;
        }
    }
}

// ---------------------------------------------------------------------------
// Feature build: gather + pairwise dots -> fp16 hi/lo (padded to K1P)
// one block (256 thr) per batch row
// ---------------------------------------------------------------------------
__global__ __launch_bounds__(256)
void build_features_kernel(const int* __restrict__ x,
                           const float* __restrict__ emb,
                           f16* __restrict__ hhi, f16* __restrict__ hlo) {
    __shared__ float e[NFEAT][68];     // 272B row stride: float4-aligned
    __shared__ int idx[NFEAT];
    const int b = blockIdx.x;
    const int t = threadIdx.x;
    if (t < NFEAT) idx[t] = x[b * NFEAT + t];
    __syncthreads();

    const size_t base = (size_t)b * K1P;

    // gather: 8 threads per feature, 8 elems per thread, float4 loads
    {
        const int f = t >> 3, d0 = (t & 7) * 8;
        const float* src = emb + ((size_t)f * VOCAB + idx[f]) * EDIM + d0;
        const float4 v0 = *(const float4*)src;
        const float4 v1 = *(const float4*)(src + 4);
        *(float4*)&e[f][d0]     = v0;
        *(float4*)&e[f][d0 + 4] = v1;

        float vv[8] = {v0.x, v0.y, v0.z, v0.w, v1.x, v1.y, v1.z, v1.w};
        __half2 ph[4], pl[4];
        #pragma unroll
        for (int k = 0; k < 4; k++) {
            f16 h0, l0, h1, l1;
            split_f16(vv[2 * k + 0], h0, l0);
            split_f16(vv[2 * k + 1], h1, l1);
            ph[k] = __halves2half2(h0, h1);
            pl[k] = __halves2half2(l0, l1);
        }
        *(uint4*)(hhi + base + f * EDIM + d0) = *(uint4*)ph;
        *(uint4*)(hlo + base + f * EDIM + d0) = *(uint4*)pl;
    }
    __syncthreads();

    // pairwise dots via lookup table + float4 smem reads
    for (int p = t; p < NPAIR; p += 256) {
        const int pr = g_pairs[p];
        const int i = pr >> 8, j = pr & 255;
        float sum = 0.f;
        #pragma unroll
        for (int d = 0; d < EDIM; d += 4) {
            const float4 a = *(const float4*)&e[i][d];
            const float4 c = *(const float4*)&e[j][d];
            sum += a.x * c.x + a.y * c.y + a.z * c.z + a.w * c.w;
        }
        f16 h, l; split_f16(sum, h, l);
        hhi[base + NFEAT * EDIM + p] = h;
        hlo[base + NFEAT * EDIM + p] = l;
    }
    if (t < K1P - DIN) {
        hhi[base + DIN + t] = __float2half(0.f);
        hlo[base + DIN + t] = __float2half(0.f);
    }
}

// ---------------------------------------------------------------------------
// Split-precision fp16 tensor-core GEMM: C[M,N] = act( A @ B^T + bias )
//   A: [M,Kp] hi/lo fp16 K-major;  B: [Npad,Kp] hi/lo fp16 K-major (W^T)
//   acc = Ahi*Bhi + Ahi*Blo + Alo*Bhi  (fp32 accumulate)
// BM=128, BN=128, BK=32; 256 threads, 8 warps 4(m) x 2(n); warp tile 32x64.
// 3-stage cp.async pipeline.
// ACT==1: relu -> fp16 hi/lo (Chi/Clo, stride ldc).  ACT==2: sigmoid -> fp32 Cf.
// ---------------------------------------------------------------------------
#define BM 128
#define BN 128
#define BKC 32
#define SPAD 40                         // halfs per smem row = 80B (16B-aligned)
#define TILE_BYTES (BM * SPAD * 2)      // 10240
#define STAGE_BYTES (4 * TILE_BYTES)    // 40960  (Ahi, Alo, Bhi, Blo)
#define NSTAGE 3
#define SMEM_TOTAL (NSTAGE * STAGE_BYTES)   // 122880

template<int ACT>
__global__ __launch_bounds__(256)
void mma_gemm_kernel(const f16* __restrict__ Ahi, const f16* __restrict__ Alo,
                     const f16* __restrict__ Bhi, const f16* __restrict__ Blo,
                     const float* __restrict__ bias,
                     f16* __restrict__ Chi, f16* __restrict__ Clo,
                     float* __restrict__ Cf,
                     int Kp, int ldc, int nchunk) {
    extern __shared__ __align__(16) char smem[];

    const int tid  = threadIdx.x;
    const int lane = tid & 31;
    const int wid  = tid >> 5;
    const int wm   = (wid & 3) * 32;    // warp m offset
    const int wn   = (wid >> 2) * 64;   // warp n offset
    const int row0 = blockIdx.y * BM;
    const int col0 = blockIdx.x * BN;

    const int la_row = lane & 15;
    const int la_col = (lane >> 4) << 3;
    const int lb_row = (lane & 7) + ((lane >> 4) << 3);
    const int lb_col = ((lane >> 3) & 1) << 3;

    float acc[2][8][4];
    #pragma unroll
    for (int mi = 0; mi < 2; mi++)
        #pragma unroll
        for (int nb = 0; nb < 8; nb++)
            #pragma unroll
            for (int q = 0; q < 4; q++) acc[mi][nb][q] = 0.f;

    auto load_stage = [&](int s, int kc) {
        char* st = smem + s * STAGE_BYTES;
        const int k0 = kc * BKC;
        #pragma unroll
        for (int j = 0; j < 2; j++) {
            const int c = j * 256 + tid;
            const int r = c >> 2, sg = c & 3;
            const uint32_t so = (uint32_t)(r * (SPAD * 2) + sg * 16);
            const size_t gA = (size_t)(row0 + r) * Kp + k0 + sg * 8;
            const size_t gB = (size_t)(col0 + r) * Kp + k0 + sg * 8;
            cp_async16(smem_u32(st + so), Ahi + gA);
            cp_async16(smem_u32(st + TILE_BYTES + so), Alo + gA);
            cp_async16(smem_u32(st + 2 * TILE_BYTES + so), Bhi + gB);
            cp_async16(smem_u32(st + 3 * TILE_BYTES + so), Blo + gB);
        }
        asm volatile("cp.async.commit_group;\n" ::: "memory");
    };

    load_stage(0, 0);
    load_stage(1, 1);

    for (int i = 0; i < nchunk; i++) {
        if (i + 2 < nchunk) {
            load_stage((i + 2) % NSTAGE, i + 2);
            asm volatile("cp.async.wait_group 2;\n" ::: "memory");
        } else if (i + 2 == nchunk) {
            asm volatile("cp.async.wait_group 1;\n" ::: "memory");
        } else {
            asm volatile("cp.async.wait_group 0;\n" ::: "memory");
        }
        __syncthreads();

        const char* st = smem + (i % NSTAGE) * STAGE_BYTES;
        const uint32_t sAhi = smem_u32(st);
        const uint32_t sAlo = sAhi + TILE_BYTES;
        const uint32_t sBhi = sAhi + 2 * TILE_BYTES;
        const uint32_t sBlo = sAhi + 3 * TILE_BYTES;

        #pragma unroll
        for (int ks = 0; ks < BKC; ks += 16) {
            uint32_t ah[2][4], al[2][4], bh[4][4], bl[4][4];
            #pragma unroll
            for (int mi = 0; mi < 2; mi++) {
                const uint32_t off =
                    (uint32_t)(((wm + mi * 16 + la_row) * SPAD + ks + la_col) * 2);
                ldsm4(sAhi + off, ah[mi][0], ah[mi][1], ah[mi][2], ah[mi][3]);
                ldsm4(sAlo + off, al[mi][0], al[mi][1], al[mi][2], al[mi][3]);
            }
            #pragma unroll
            for (int np = 0; np < 4; np++) {
                const uint32_t off =
                    (uint32_t)(((wn + np * 16 + lb_row) * SPAD + ks + lb_col) * 2);
                ldsm4(sBhi + off, bh[np][0], bh[np][1], bh[np][2], bh[np][3]);
                ldsm4(sBlo + off, bl[np][0], bl[np][1], bl[np][2], bl[np][3]);
            }
            #pragma unroll
            for (int mi = 0; mi < 2; mi++) {
                #pragma unroll
                for (int nb = 0; nb < 8; nb++) {
                    const uint32_t b0h = bh[nb >> 1][(nb & 1) * 2];
                    const uint32_t b1h = bh[nb >> 1][(nb & 1) * 2 + 1];
                    const uint32_t b0l = bl[nb >> 1][(nb & 1) * 2];
                    const uint32_t b1l = bl[nb >> 1][(nb & 1) * 2 + 1];
                    mma_fp16(acc[mi][nb], ah[mi], b0h, b1h);   // hi*hi
                    mma_fp16(acc[mi][nb], ah[mi], b0l, b1l);   // hi*lo
                    mma_fp16(acc[mi][nb], al[mi], b0h, b1h);   // lo*hi
                }
            }
        }
        __syncthreads();
    }

    // -------- epilogue --------
    #pragma unroll
    for (int mi = 0; mi < 2; mi++) {
        #pragma unroll
        for (int nb = 0; nb < 8; nb++) {
            const int rg = row0 + wm + mi * 16 + (lane >> 2);
            const int cg = col0 + wn + nb * 8 + (lane & 3) * 2;
            float b0 = 0.f, b1 = 0.f;
            if (ACT == 2) {
                if (cg < DOUT)     b0 = bias[cg];
                if (cg + 1 < DOUT) b1 = bias[cg + 1];
            } else {
                b0 = bias[cg];
                b1 = bias[cg + 1];
            }
            const float* a = acc[mi][nb];
            #pragma unroll
            for (int h = 0; h < 2; h++) {
                const int r = rg + h * 8;
                float v0 = a[h * 2 + 0] + b0;
                float v1 = a[h * 2 + 1] + b1;
                if (ACT == 1) {
                    v0 = fmaxf(v0, 0.f);
                    v1 = fmaxf(v1, 0.f);
                    f16 h0, l0, h1, l1;
                    split_f16(v0, h0, l0);
                    split_f16(v1, h1, l1);
                    *(__half2*)(Chi + (size_t)r * ldc + cg) = __halves2half2(h0, h1);
                    *(__half2*)(Clo + (size_t)r * ldc + cg) = __halves2half2(l0, l1);
                } else {
                    if (cg + 2 <= DOUT) {
                        float2 o;
                        o.x = 1.f / (1.f + __expf(-v0));
                        o.y = 1.f / (1.f + __expf(-v1));
                        *(float2*)(Cf + (size_t)r * DOUT + cg) = o;
                    }
                }
            }
        }
    }
}

// ---------------------------------------------------------------------------
extern "C" void kernel_launch(void* const* d_in, const int* in_sizes, int n_in,
                              void* d_out, int out_size) {
    const int*   x   = (const int*)  d_in[0];
    const float* emb = (const float*)d_in[1];
    const float* W1  = (const float*)d_in[2];
    const float* b1  = (const float*)d_in[3];
    const float* W2  = (const float*)d_in[4];
    const float* b2  = (const float*)d_in[5];
    const float* W3  = (const float*)d_in[6];
    const float* b3  = (const float*)d_in[7];
    float* out = (float*)d_out;

    f16 *h0hi, *h0lo, *h1hi, *h1lo, *h2hi, *h2lo;
    f16 *w1hi, *w1lo, *w2hi, *w2lo, *w3hi, *w3lo;
    cudaGetSymbolAddress((void**)&h0hi, g_h0hi);
    cudaGetSymbolAddress((void**)&h0lo, g_h0lo);
    cudaGetSymbolAddress((void**)&h1hi, g_h1hi);
    cudaGetSymbolAddress((void**)&h1lo, g_h1lo);
    cudaGetSymbolAddress((void**)&h2hi, g_h2hi);
    cudaGetSymbolAddress((void**)&h2lo, g_h2lo);
    cudaGetSymbolAddress((void**)&w1hi, g_W1hi);
    cudaGetSymbolAddress((void**)&w1lo, g_W1lo);
    cudaGetSymbolAddress((void**)&w2hi, g_W2hi);
    cudaGetSymbolAddress((void**)&w2lo, g_W2lo);
    cudaGetSymbolAddress((void**)&w3hi, g_W3hi);
    cudaGetSymbolAddress((void**)&w3lo, g_W3lo);

    cudaFuncSetAttribute(mma_gemm_kernel<1>,
                         cudaFuncAttributeMaxDynamicSharedMemorySize, SMEM_TOTAL);
    cudaFuncSetAttribute(mma_gemm_kernel<2>,
                         cudaFuncAttributeMaxDynamicSharedMemorySize, SMEM_TOTAL);

    init_pairs_kernel<<<1, 512>>>();
    {   // weight conversion (transpose + hi/lo split + zero pad)
        dim3 blk(32, 8);
        convert_w_kernel<<<dim3(DH1 / 32, K1P / 32), blk>>>(W1, w1hi, w1lo, DIN, DH1, K1P, DH1);
        convert_w_kernel<<<dim3(DH2 / 32, DH1 / 32), blk>>>(W2, w2hi, w2lo, DH1, DH2, DH1, DH2);
        convert_w_kernel<<<dim3(N3P / 32, DH2 / 32), blk>>>(W3, w3hi, w3lo, DH2, DOUT, DH2, N3P);
    }

    build_features_kernel<<<BATCH, 256>>>(x, emb, h0hi, h0lo);

    // layer 1: [8192,2560] x [1024,2560]^T -> relu -> h1 (fp16 hi/lo)
    mma_gemm_kernel<1><<<dim3(DH1 / BN, BATCH / BM), 256, SMEM_TOTAL>>>(
        h0hi, h0lo, w1hi, w1lo, b1, h1hi, h1lo, nullptr, K1P, DH1, K1P / BKC);
    // layer 2: [8192,1024] x [512,1024]^T -> relu -> h2
    mma_gemm_kernel<1><<<dim3(DH2 / BN, BATCH / BM), 256, SMEM_TOTAL>>>(
        h1hi, h1lo, w2hi, w2lo, b2, h2hi, h2lo, nullptr, DH1, DH2, DH1 / BKC);
    // layer 3: [8192,512] x [1024,512]^T -> sigmoid -> out fp32 (cols < 1000)
    mma_gemm_kernel<2><<<dim3(N3P / BN, BATCH / BM), 256, SMEM_TOTAL>>>(
        h2hi, h2lo, w3hi, w3lo, b3, nullptr, nullptr, out, DH2, 0, DH2 / BKC);
}

// round 5
// speedup vs baseline: 1.1526x; 1.1526x over previous
#include <cuda_runtime.h>
#include <cuda_fp16.h>
#include <cstdint>

#define BATCH 8192
#define NFEAT 32
#define EDIM  64
#define VOCAB 1000
#define NPAIR 496
#define DIN   2544
#define K1P   2560
#define DH1   1024
#define DH2   512
#define DOUT  1000
#define N3P   1024

typedef __half f16;

// ---------------- scratch (device globals; no runtime allocation) ----------
__device__ f16 g_h0hi[(size_t)BATCH * K1P];
__device__ f16 g_h0lo[(size_t)BATCH * K1P];
__device__ f16 g_h1hi[(size_t)BATCH * DH1];
__device__ f16 g_h1lo[(size_t)BATCH * DH1];
__device__ f16 g_h2hi[(size_t)BATCH * DH2];
__device__ f16 g_h2lo[(size_t)BATCH * DH2];
__device__ f16 g_W1hi[(size_t)DH1 * K1P];
__device__ f16 g_W1lo[(size_t)DH1 * K1P];
__device__ f16 g_W2hi[(size_t)DH2 * DH1];
__device__ f16 g_W2lo[(size_t)DH2 * DH1];
__device__ f16 g_W3hi[(size_t)N3P * DH2];
__device__ f16 g_W3lo[(size_t)N3P * DH2];
__device__ int g_pairs[NPAIR];

// ---------------- helpers ---------------------------------------------------
__device__ __forceinline__ uint32_t smem_u32(const void* p) {
    return (uint32_t)__cvta_generic_to_shared(p);
}
__device__ __forceinline__ void cp_async16(uint32_t dst, const void* src) {
    asm volatile("cp.async.cg.shared.global [%0], [%1], 16;\n" :: "r"(dst), "l"(src));
}
__device__ __forceinline__ void split_f16(float v, f16& h, f16& l) {
    h = __float2half_rn(v);
    l = __float2half_rn(v - __half2float(h));
}
__device__ __forceinline__ void ldsm4(uint32_t addr, uint32_t& r0, uint32_t& r1,
                                      uint32_t& r2, uint32_t& r3) {
    asm volatile("ldmatrix.sync.aligned.m8n8.x4.shared.b16 {%0,%1,%2,%3}, [%4];\n"
                 : "=r"(r0), "=r"(r1), "=r"(r2), "=r"(r3) : "r"(addr));
}
__device__ __forceinline__ void mma_fp16(float c[4], const uint32_t a[4],
                                         uint32_t b0, uint32_t b1) {
    asm volatile("mma.sync.aligned.m16n8k16.row.col.f32.f16.f16.f32 "
                 "{%0,%1,%2,%3},{%4,%5,%6,%7},{%8,%9},{%0,%1,%2,%3};\n"
                 : "+f"(c[0]), "+f"(c[1]), "+f"(c[2]), "+f"(c[3])
                 : "r"(a[0]), "r"(a[1]), "r"(a[2]), "r"(a[3]), "r"(b0), "r"(b1));
}

// ---------------------------------------------------------------------------
__global__ void init_pairs_kernel() {
    const int p = threadIdx.x;
    if (p < NPAIR) {
        int i = 0, s = 0;
        while (p >= s + (NFEAT - 1 - i)) { s += NFEAT - 1 - i; i++; }
        g_pairs[p] = (i << 8) | (i + 1 + (p - s));
    }
}

// ---------------------------------------------------------------------------
// Weight conversion: W[K][N] fp32 -> transposed hi/lo fp16 [Npad][Kpad], zero pad
// ---------------------------------------------------------------------------
__global__ void convert_w_kernel(const float* __restrict__ W,
                                 f16* __restrict__ hi, f16* __restrict__ lo,
                                 int K, int N, int Kpad, int Npad) {
    __shared__ float t[32][33];
    const int n0 = blockIdx.x * 32;
    const int k0 = blockIdx.y * 32;
    for (int r = threadIdx.y; r < 32; r += 8) {
        int k = k0 + r, n = n0 + threadIdx.x;
        t[r][threadIdx.x] = (k < K && n < N) ? W[(size_t)k * N + n] : 0.f;
    }
    __syncthreads();
    for (int r = threadIdx.y; r < 32; r += 8) {
        int n = n0 + r, k = k0 + threadIdx.x;
        if (n < Npad && k < Kpad) {
            float v = t[threadIdx.x][r];
            f16 h, l; split_f16(v, h, l);
            hi[(size_t)n * Kpad + k] = h;
            lo[(size_t)n * Kpad + k] = l;
        }
    }
}

// ---------------------------------------------------------------------------
// Feature build: gather + pairwise dots -> fp16 hi/lo (padded to K1P)
// ---------------------------------------------------------------------------
__global__ __launch_bounds__(256)
void build_features_kernel(const int* __restrict__ x,
                           const float* __restrict__ emb,
                           f16* __restrict__ hhi, f16* __restrict__ hlo) {
    __shared__ float e[NFEAT][68];     // float4-aligned row stride
    __shared__ int idx[NFEAT];
    const int b = blockIdx.x;
    const int t = threadIdx.x;
    if (t < NFEAT) idx[t] = x[b * NFEAT + t];
    __syncthreads();

    const size_t base = (size_t)b * K1P;

    {   // gather: 8 threads per feature, 8 elems per thread, float4 loads
        const int f = t >> 3, d0 = (t & 7) * 8;
        const float* src = emb + ((size_t)f * VOCAB + idx[f]) * EDIM + d0;
        const float4 v0 = *(const float4*)src;
        const float4 v1 = *(const float4*)(src + 4);
        *(float4*)&e[f][d0]     = v0;
        *(float4*)&e[f][d0 + 4] = v1;

        float vv[8] = {v0.x, v0.y, v0.z, v0.w, v1.x, v1.y, v1.z, v1.w};
        __half2 ph[4], pl[4];
        #pragma unroll
        for (int k = 0; k < 4; k++) {
            f16 h0, l0, h1, l1;
            split_f16(vv[2 * k + 0], h0, l0);
            split_f16(vv[2 * k + 1], h1, l1);
            ph[k] = __halves2half2(h0, h1);
            pl[k] = __halves2half2(l0, l1);
        }
        *(uint4*)(hhi + base + f * EDIM + d0) = *(uint4*)ph;
        *(uint4*)(hlo + base + f * EDIM + d0) = *(uint4*)pl;
    }
    __syncthreads();

    for (int p = t; p < NPAIR; p += 256) {
        const int pr = g_pairs[p];
        const int i = pr >> 8, j = pr & 255;
        float sum = 0.f;
        #pragma unroll
        for (int d = 0; d < EDIM; d += 4) {
            const float4 a = *(const float4*)&e[i][d];
            const float4 c = *(const float4*)&e[j][d];
            sum += a.x * c.x + a.y * c.y + a.z * c.z + a.w * c.w;
        }
        f16 h, l; split_f16(sum, h, l);
        hhi[base + NFEAT * EDIM + p] = h;
        hlo[base + NFEAT * EDIM + p] = l;
    }
    if (t < K1P - DIN) {
        hhi[base + DIN + t] = __float2half(0.f);
        hlo[base + DIN + t] = __float2half(0.f);
    }
}

// ---------------------------------------------------------------------------
// Split-precision fp16 tensor-core GEMM: C[M,N] = act( A @ B^T + bias )
//   acc = Ahi*Bhi + Ahi*Blo + Alo*Bhi  (fp32 accumulate)
// BM=128, BN=64, BK=32; 256 threads, warps 4(m) x 2(n), warp tile 32x32.
// 3-stage cp.async ring; 2 CTAs/SM.
// ---------------------------------------------------------------------------
#define BM 128
#define BN 64
#define BKC 32
#define SPAD 40                           // halfs per row = 80B (16B-aligned)
#define A_BYTES (BM * SPAD * 2)           // 10240
#define B_BYTES (BN * SPAD * 2)           // 5120
#define STAGE_BYTES (2 * A_BYTES + 2 * B_BYTES)   // 30720
#define NSTAGE 3
#define SMEM_TOTAL (NSTAGE * STAGE_BYTES)          // 92160

template<int ACT>
__global__ __launch_bounds__(256, 2)
void mma_gemm_kernel(const f16* __restrict__ Ahi, const f16* __restrict__ Alo,
                     const f16* __restrict__ Bhi, const f16* __restrict__ Blo,
                     const float* __restrict__ bias,
                     f16* __restrict__ Chi, f16* __restrict__ Clo,
                     float* __restrict__ Cf,
                     int Kp, int ldc, int nchunk) {
    extern __shared__ __align__(16) char smem[];

    const int tid  = threadIdx.x;
    const int lane = tid & 31;
    const int wid  = tid >> 5;
    const int wm   = (wid >> 1) * 32;
    const int wn   = (wid & 1) * 32;
    const int row0 = blockIdx.y * BM;
    const int col0 = blockIdx.x * BN;

    const int la_row = lane & 15;
    const int la_col = (lane >> 4) << 3;
    const int lb_row = (lane & 7) + ((lane >> 4) << 3);
    const int lb_col = ((lane >> 3) & 1) << 3;

    float acc[2][4][4];
    #pragma unroll
    for (int mi = 0; mi < 2; mi++)
        #pragma unroll
        for (int nb = 0; nb < 4; nb++)
            #pragma unroll
            for (int q = 0; q < 4; q++) acc[mi][nb][q] = 0.f;

    auto load_stage = [&](int s, int kc) {
        char* st = smem + s * STAGE_BYTES;
        const int k0 = kc * BKC;
        #pragma unroll
        for (int p = 0; p < 2; p++) {          // A: 128 rows x 4 segs
            const int c = tid + p * 256;
            const int r = c >> 2, sg = c & 3;
            const uint32_t so = (uint32_t)(r * (SPAD * 2) + sg * 16);
            const size_t g = (size_t)(row0 + r) * Kp + k0 + sg * 8;
            cp_async16(smem_u32(st + so), Ahi + g);
            cp_async16(smem_u32(st + A_BYTES + so), Alo + g);
        }
        {                                       // B: 64 rows x 4 segs
            const int r = tid >> 2, sg = tid & 3;
            const uint32_t so = (uint32_t)(r * (SPAD * 2) + sg * 16);
            const size_t g = (size_t)(col0 + r) * Kp + k0 + sg * 8;
            cp_async16(smem_u32(st + 2 * A_BYTES + so), Bhi + g);
            cp_async16(smem_u32(st + 2 * A_BYTES + B_BYTES + so), Blo + g);
        }
        asm volatile("cp.async.commit_group;\n" ::: "memory");
    };

    load_stage(0, 0);
    load_stage(1, 1);

    for (int i = 0; i < nchunk; i++) {
        if (i + 2 < nchunk) {
            load_stage((i + 2) % NSTAGE, i + 2);
            asm volatile("cp.async.wait_group 2;\n" ::: "memory");
        } else if (i + 2 == nchunk) {
            asm volatile("cp.async.wait_group 1;\n" ::: "memory");
        } else {
            asm volatile("cp.async.wait_group 0;\n" ::: "memory");
        }
        __syncthreads();

        const char* st = smem + (i % NSTAGE) * STAGE_BYTES;
        const uint32_t sAhi = smem_u32(st);
        const uint32_t sAlo = sAhi + A_BYTES;
        const uint32_t sBhi = sAhi + 2 * A_BYTES;
        const uint32_t sBlo = sAhi + 2 * A_BYTES + B_BYTES;

        #pragma unroll
        for (int ks = 0; ks < BKC; ks += 16) {
            uint32_t ah[2][4], al[2][4], bh[2][4], bl[2][4];
            #pragma unroll
            for (int mi = 0; mi < 2; mi++) {
                const uint32_t off =
                    (uint32_t)(((wm + mi * 16 + la_row) * SPAD + ks + la_col) * 2);
                ldsm4(sAhi + off, ah[mi][0], ah[mi][1], ah[mi][2], ah[mi][3]);
                ldsm4(sAlo + off, al[mi][0], al[mi][1], al[mi][2], al[mi][3]);
            }
            #pragma unroll
            for (int np = 0; np < 2; np++) {
                const uint32_t off =
                    (uint32_t)(((wn + np * 16 + lb_row) * SPAD + ks + lb_col) * 2);
                ldsm4(sBhi + off, bh[np][0], bh[np][1], bh[np][2], bh[np][3]);
                ldsm4(sBlo + off, bl[np][0], bl[np][1], bl[np][2], bl[np][3]);
            }
            #pragma unroll
            for (int mi = 0; mi < 2; mi++) {
                #pragma unroll
                for (int nb = 0; nb < 4; nb++) {
                    const uint32_t b0h = bh[nb >> 1][(nb & 1) * 2];
                    const uint32_t b1h = bh[nb >> 1][(nb & 1) * 2 + 1];
                    const uint32_t b0l = bl[nb >> 1][(nb & 1) * 2];
                    const uint32_t b1l = bl[nb >> 1][(nb & 1) * 2 + 1];
                    mma_fp16(acc[mi][nb], ah[mi], b0h, b1h);   // hi*hi
                    mma_fp16(acc[mi][nb], ah[mi], b0l, b1l);   // hi*lo
                    mma_fp16(acc[mi][nb], al[mi], b0h, b1h);   // lo*hi
                }
            }
        }
        __syncthreads();
    }

    // -------- epilogue --------
    #pragma unroll
    for (int mi = 0; mi < 2; mi++) {
        #pragma unroll
        for (int nb = 0; nb < 4; nb++) {
            const int rg = row0 + wm + mi * 16 + (lane >> 2);
            const int cg = col0 + wn + nb * 8 + (lane & 3) * 2;
            float b0 = 0.f, b1 = 0.f;
            if (ACT == 2) {
                if (cg < DOUT)     b0 = bias[cg];
                if (cg + 1 < DOUT) b1 = bias[cg + 1];
            } else {
                b0 = bias[cg];
                b1 = bias[cg + 1];
            }
            const float* a = acc[mi][nb];
            #pragma unroll
            for (int h = 0; h < 2; h++) {
                const int r = rg + h * 8;
                float v0 = a[h * 2 + 0] + b0;
                float v1 = a[h * 2 + 1] + b1;
                if (ACT == 1) {
                    v0 = fmaxf(v0, 0.f);
                    v1 = fmaxf(v1, 0.f);
                    f16 h0, l0, h1, l1;
                    split_f16(v0, h0, l0);
                    split_f16(v1, h1, l1);
                    *(__half2*)(Chi + (size_t)r * ldc + cg) = __halves2half2(h0, h1);
                    *(__half2*)(Clo + (size_t)r * ldc + cg) = __halves2half2(l0, l1);
                } else {
                    if (cg + 2 <= DOUT) {
                        float2 o;
                        o.x = 1.f / (1.f + __expf(-v0));
                        o.y = 1.f / (1.f + __expf(-v1));
                        *(float2*)(Cf + (size_t)r * DOUT + cg) = o;
                    }
                }
            }
        }
    }
}

// ---------------------------------------------------------------------------
extern "C" void kernel_launch(void* const* d_in, const int* in_sizes, int n_in,
                              void* d_out, int out_size) {
    const int*   x   = (const int*)  d_in[0];
    const float* emb = (const float*)d_in[1];
    const float* W1  = (const float*)d_in[2];
    const float* b1  = (const float*)d_in[3];
    const float* W2  = (const float*)d_in[4];
    const float* b2  = (const float*)d_in[5];
    const float* W3  = (const float*)d_in[6];
    const float* b3  = (const float*)d_in[7];
    float* out = (float*)d_out;

    f16 *h0hi, *h0lo, *h1hi, *h1lo, *h2hi, *h2lo;
    f16 *w1hi, *w1lo, *w2hi, *w2lo, *w3hi, *w3lo;
    cudaGetSymbolAddress((void**)&h0hi, g_h0hi);
    cudaGetSymbolAddress((void**)&h0lo, g_h0lo);
    cudaGetSymbolAddress((void**)&h1hi, g_h1hi);
    cudaGetSymbolAddress((void**)&h1lo, g_h1lo);
    cudaGetSymbolAddress((void**)&h2hi, g_h2hi);
    cudaGetSymbolAddress((void**)&h2lo, g_h2lo);
    cudaGetSymbolAddress((void**)&w1hi, g_W1hi);
    cudaGetSymbolAddress((void**)&w1lo, g_W1lo);
    cudaGetSymbolAddress((void**)&w2hi, g_W2hi);
    cudaGetSymbolAddress((void**)&w2lo, g_W2lo);
    cudaGetSymbolAddress((void**)&w3hi, g_W3hi);
    cudaGetSymbolAddress((void**)&w3lo, g_W3lo);

    cudaFuncSetAttribute(mma_gemm_kernel<1>,
                         cudaFuncAttributeMaxDynamicSharedMemorySize, SMEM_TOTAL);
    cudaFuncSetAttribute(mma_gemm_kernel<2>,
                         cudaFuncAttributeMaxDynamicSharedMemorySize, SMEM_TOTAL);

    init_pairs_kernel<<<1, 512>>>();
    {
        dim3 blk(32, 8);
        convert_w_kernel<<<dim3(DH1 / 32, K1P / 32), blk>>>(W1, w1hi, w1lo, DIN, DH1, K1P, DH1);
        convert_w_kernel<<<dim3(DH2 / 32, DH1 / 32), blk>>>(W2, w2hi, w2lo, DH1, DH2, DH1, DH2);
        convert_w_kernel<<<dim3(N3P / 32, DH2 / 32), blk>>>(W3, w3hi, w3lo, DH2, DOUT, DH2, N3P);
    }

    build_features_kernel<<<BATCH, 256>>>(x, emb, h0hi, h0lo);

    mma_gemm_kernel<1><<<dim3(DH1 / BN, BATCH / BM), 256, SMEM_TOTAL>>>(
        h0hi, h0lo, w1hi, w1lo, b1, h1hi, h1lo, nullptr, K1P, DH1, K1P / BKC);
    mma_gemm_kernel<1><<<dim3(DH2 / BN, BATCH / BM), 256, SMEM_TOTAL>>>(
        h1hi, h1lo, w2hi, w2lo, b2, h2hi, h2lo, nullptr, DH1, DH2, DH1 / BKC);
    mma_gemm_kernel<2><<<dim3(N3P / BN, BATCH / BM), 256, SMEM_TOTAL>>>(
        h2hi, h2lo, w3hi, w3lo, b3, nullptr, nullptr, out, DH2, 0, DH2 / BKC);
}

// round 6
// speedup vs baseline: 1.5742x; 1.3658x over previous
#include <cuda_runtime.h>
#include <cuda_fp16.h>
#include <cstdint>

#define BATCH 8192
#define NFEAT 32
#define EDIM  64
#define VOCAB 1000
#define NPAIR 496
#define DIN   2544
#define K1P   2560
#define DH1   1024
#define DH2   512
#define DOUT  1000
#define N3P   1024

typedef __half f16;

// ---------------- scratch (device globals; no runtime allocation) ----------
__device__ f16 g_h0[(size_t)BATCH * K1P];
__device__ f16 g_h1[(size_t)BATCH * DH1];
__device__ f16 g_h2[(size_t)BATCH * DH2];
__device__ f16 g_W1hi[(size_t)DH1 * K1P];
__device__ f16 g_W1lo[(size_t)DH1 * K1P];
__device__ f16 g_W2hi[(size_t)DH2 * DH1];
__device__ f16 g_W2lo[(size_t)DH2 * DH1];
__device__ f16 g_W3hi[(size_t)N3P * DH2];
__device__ f16 g_W3lo[(size_t)N3P * DH2];
__device__ int g_pairs[NPAIR];

// ---------------- helpers ---------------------------------------------------
__device__ __forceinline__ uint32_t smem_u32(const void* p) {
    return (uint32_t)__cvta_generic_to_shared(p);
}
__device__ __forceinline__ void cp_async16(uint32_t dst, const void* src) {
    asm volatile("cp.async.cg.shared.global [%0], [%1], 16;\n" :: "r"(dst), "l"(src));
}
__device__ __forceinline__ void split_f16(float v, f16& h, f16& l) {
    h = __float2half_rn(v);
    l = __float2half_rn(v - __half2float(h));
}
__device__ __forceinline__ void ldsm4(uint32_t addr, uint32_t& r0, uint32_t& r1,
                                      uint32_t& r2, uint32_t& r3) {
    asm volatile("ldmatrix.sync.aligned.m8n8.x4.shared.b16 {%0,%1,%2,%3}, [%4];\n"
                 : "=r"(r0), "=r"(r1), "=r"(r2), "=r"(r3) : "r"(addr));
}
__device__ __forceinline__ void mma_fp16(float c[4], const uint32_t a[4],
                                         uint32_t b0, uint32_t b1) {
    asm volatile("mma.sync.aligned.m16n8k16.row.col.f32.f16.f16.f32 "
                 "{%0,%1,%2,%3},{%4,%5,%6,%7},{%8,%9},{%0,%1,%2,%3};\n"
                 : "+f"(c[0]), "+f"(c[1]), "+f"(c[2]), "+f"(c[3])
                 : "r"(a[0]), "r"(a[1]), "r"(a[2]), "r"(a[3]), "r"(b0), "r"(b1));
}

// ---------------------------------------------------------------------------
__global__ void init_pairs_kernel() {
    const int p = threadIdx.x;
    if (p < NPAIR) {
        int i = 0, s = 0;
        while (p >= s + (NFEAT - 1 - i)) { s += NFEAT - 1 - i; i++; }
        g_pairs[p] = (i << 8) | (i + 1 + (p - s));
    }
}

// ---------------------------------------------------------------------------
// Weight conversion: W[K][N] fp32 -> transposed hi/lo fp16 [Npad][Kpad], zero pad
// ---------------------------------------------------------------------------
__global__ void convert_w_kernel(const float* __restrict__ W,
                                 f16* __restrict__ hi, f16* __restrict__ lo,
                                 int K, int N, int Kpad, int Npad) {
    __shared__ float t[32][33];
    const int n0 = blockIdx.x * 32;
    const int k0 = blockIdx.y * 32;
    for (int r = threadIdx.y; r < 32; r += 8) {
        int k = k0 + r, n = n0 + threadIdx.x;
        t[r][threadIdx.x] = (k < K && n < N) ? W[(size_t)k * N + n] : 0.f;
    }
    __syncthreads();
    for (int r = threadIdx.y; r < 32; r += 8) {
        int n = n0 + r, k = k0 + threadIdx.x;
        if (n < Npad && k < Kpad) {
            float v = t[threadIdx.x][r];
            f16 h, l; split_f16(v, h, l);
            hi[(size_t)n * Kpad + k] = h;
            lo[(size_t)n * Kpad + k] = l;
        }
    }
}

// ---------------------------------------------------------------------------
// Feature build: gather + pairwise dots -> fp16 (padded to K1P)
// ---------------------------------------------------------------------------
__global__ __launch_bounds__(256)
void build_features_kernel(const int* __restrict__ x,
                           const float* __restrict__ emb,
                           f16* __restrict__ h0) {
    __shared__ float e[NFEAT][68];     // float4-aligned row stride
    __shared__ int idx[NFEAT];
    const int b = blockIdx.x;
    const int t = threadIdx.x;
    if (t < NFEAT) idx[t] = x[b * NFEAT + t];
    __syncthreads();

    const size_t base = (size_t)b * K1P;

    {   // gather: 8 threads per feature, 8 elems per thread, float4 loads
        const int f = t >> 3, d0 = (t & 7) * 8;
        const float* src = emb + ((size_t)f * VOCAB + idx[f]) * EDIM + d0;
        const float4 v0 = *(const float4*)src;
        const float4 v1 = *(const float4*)(src + 4);
        *(float4*)&e[f][d0]     = v0;
        *(float4*)&e[f][d0 + 4] = v1;

        __half2 ph[4];
        ph[0] = __floats2half2_rn(v0.x, v0.y);
        ph[1] = __floats2half2_rn(v0.z, v0.w);
        ph[2] = __floats2half2_rn(v1.x, v1.y);
        ph[3] = __floats2half2_rn(v1.z, v1.w);
        *(uint4*)(h0 + base + f * EDIM + d0) = *(uint4*)ph;
    }
    __syncthreads();

    for (int p = t; p < NPAIR; p += 256) {
        const int pr = g_pairs[p];
        const int i = pr >> 8, j = pr & 255;
        float sum = 0.f;
        #pragma unroll
        for (int d = 0; d < EDIM; d += 4) {
            const float4 a = *(const float4*)&e[i][d];
            const float4 c = *(const float4*)&e[j][d];
            sum += a.x * c.x + a.y * c.y + a.z * c.z + a.w * c.w;
        }
        h0[base + NFEAT * EDIM + p] = __float2half_rn(sum);
    }
    if (t < K1P - DIN) h0[base + DIN + t] = __float2half(0.f);
}

// ---------------------------------------------------------------------------
// 2-term split GEMM: C[M,N] = act( A @ (Bhi+Blo)^T + bias )
//   A: fp16 [M,Kp] K-major;  B: hi/lo fp16 [Npad,Kp] K-major (W^T exact to 2^-22)
//   acc = A*Bhi + A*Blo  (fp32 accumulate); only activation rounding error.
// BM=128, BN=64, BK=32; 256 threads, warps 4(m) x 2(n), warp tile 32x32.
// 3-stage cp.async ring; 2 CTAs/SM.
// ---------------------------------------------------------------------------
#define BM 128
#define BN 64
#define BKC 32
#define SPAD 40                           // halfs per row = 80B (16B-aligned)
#define A_BYTES (BM * SPAD * 2)           // 10240
#define B_BYTES (BN * SPAD * 2)           // 5120
#define STAGE_BYTES (A_BYTES + 2 * B_BYTES)   // 20480
#define NSTAGE 3
#define SMEM_TOTAL (NSTAGE * STAGE_BYTES)     // 61440

template<int ACT>
__global__ __launch_bounds__(256, 2)
void mma_gemm_kernel(const f16* __restrict__ A,
                     const f16* __restrict__ Bhi, const f16* __restrict__ Blo,
                     const float* __restrict__ bias,
                     f16* __restrict__ Ch, float* __restrict__ Cf,
                     int Kp, int ldc, int nchunk) {
    extern __shared__ __align__(16) char smem[];

    const int tid  = threadIdx.x;
    const int lane = tid & 31;
    const int wid  = tid >> 5;
    const int wm   = (wid >> 1) * 32;
    const int wn   = (wid & 1) * 32;
    const int row0 = blockIdx.y * BM;
    const int col0 = blockIdx.x * BN;

    const int la_row = lane & 15;
    const int la_col = (lane >> 4) << 3;
    const int lb_row = (lane & 7) + ((lane >> 4) << 3);
    const int lb_col = ((lane >> 3) & 1) << 3;

    float acc[2][4][4];
    #pragma unroll
    for (int mi = 0; mi < 2; mi++)
        #pragma unroll
        for (int nb = 0; nb < 4; nb++)
            #pragma unroll
            for (int q = 0; q < 4; q++) acc[mi][nb][q] = 0.f;

    auto load_stage = [&](int s, int kc) {
        char* st = smem + s * STAGE_BYTES;
        const int k0 = kc * BKC;
        #pragma unroll
        for (int p = 0; p < 2; p++) {          // A: 128 rows x 4 segs
            const int c = tid + p * 256;
            const int r = c >> 2, sg = c & 3;
            const uint32_t so = (uint32_t)(r * (SPAD * 2) + sg * 16);
            const size_t g = (size_t)(row0 + r) * Kp + k0 + sg * 8;
            cp_async16(smem_u32(st + so), A + g);
        }
        {                                       // B: 64 rows x 4 segs, hi + lo
            const int r = tid >> 2, sg = tid & 3;
            const uint32_t so = (uint32_t)(r * (SPAD * 2) + sg * 16);
            const size_t g = (size_t)(col0 + r) * Kp + k0 + sg * 8;
            cp_async16(smem_u32(st + A_BYTES + so), Bhi + g);
            cp_async16(smem_u32(st + A_BYTES + B_BYTES + so), Blo + g);
        }
        asm volatile("cp.async.commit_group;\n" ::: "memory");
    };

    load_stage(0, 0);
    load_stage(1, 1);

    for (int i = 0; i < nchunk; i++) {
        if (i + 2 < nchunk) {
            load_stage((i + 2) % NSTAGE, i + 2);
            asm volatile("cp.async.wait_group 2;\n" ::: "memory");
        } else if (i + 2 == nchunk) {
            asm volatile("cp.async.wait_group 1;\n" ::: "memory");
        } else {
            asm volatile("cp.async.wait_group 0;\n" ::: "memory");
        }
        __syncthreads();

        const char* st = smem + (i % NSTAGE) * STAGE_BYTES;
        const uint32_t sA   = smem_u32(st);
        const uint32_t sBhi = sA + A_BYTES;
        const uint32_t sBlo = sA + A_BYTES + B_BYTES;

        #pragma unroll
        for (int ks = 0; ks < BKC; ks += 16) {
            uint32_t ar[2][4], bh[2][4], bl[2][4];
            #pragma unroll
            for (int mi = 0; mi < 2; mi++) {
                const uint32_t off =
                    (uint32_t)(((wm + mi * 16 + la_row) * SPAD + ks + la_col) * 2);
                ldsm4(sA + off, ar[mi][0], ar[mi][1], ar[mi][2], ar[mi][3]);
            }
            #pragma unroll
            for (int np = 0; np < 2; np++) {
                const uint32_t off =
                    (uint32_t)(((wn + np * 16 + lb_row) * SPAD + ks + lb_col) * 2);
                ldsm4(sBhi + off, bh[np][0], bh[np][1], bh[np][2], bh[np][3]);
                ldsm4(sBlo + off, bl[np][0], bl[np][1], bl[np][2], bl[np][3]);
            }
            #pragma unroll
            for (int mi = 0; mi < 2; mi++) {
                #pragma unroll
                for (int nb = 0; nb < 4; nb++) {
                    const uint32_t b0h = bh[nb >> 1][(nb & 1) * 2];
                    const uint32_t b1h = bh[nb >> 1][(nb & 1) * 2 + 1];
                    const uint32_t b0l = bl[nb >> 1][(nb & 1) * 2];
                    const uint32_t b1l = bl[nb >> 1][(nb & 1) * 2 + 1];
                    mma_fp16(acc[mi][nb], ar[mi], b0h, b1h);   // a * w_hi
                    mma_fp16(acc[mi][nb], ar[mi], b0l, b1l);   // a * w_lo
                }
            }
        }
        __syncthreads();
    }

    // -------- epilogue --------
    #pragma unroll
    for (int mi = 0; mi < 2; mi++) {
        #pragma unroll
        for (int nb = 0; nb < 4; nb++) {
            const int rg = row0 + wm + mi * 16 + (lane >> 2);
            const int cg = col0 + wn + nb * 8 + (lane & 3) * 2;
            float b0 = 0.f, b1 = 0.f;
            if (ACT == 2) {
                if (cg < DOUT)     b0 = bias[cg];
                if (cg + 1 < DOUT) b1 = bias[cg + 1];
            } else {
                b0 = bias[cg];
                b1 = bias[cg + 1];
            }
            const float* a = acc[mi][nb];
            #pragma unroll
            for (int h = 0; h < 2; h++) {
                const int r = rg + h * 8;
                float v0 = a[h * 2 + 0] + b0;
                float v1 = a[h * 2 + 1] + b1;
                if (ACT == 1) {
                    v0 = fmaxf(v0, 0.f);
                    v1 = fmaxf(v1, 0.f);
                    *(__half2*)(Ch + (size_t)r * ldc + cg) = __floats2half2_rn(v0, v1);
                } else {
                    if (cg + 2 <= DOUT) {
                        float2 o;
                        o.x = 1.f / (1.f + __expf(-v0));
                        o.y = 1.f / (1.f + __expf(-v1));
                        *(float2*)(Cf + (size_t)r * DOUT + cg) = o;
                    }
                }
            }
        }
    }
}

// ---------------------------------------------------------------------------
extern "C" void kernel_launch(void* const* d_in, const int* in_sizes, int n_in,
                              void* d_out, int out_size) {
    const int*   x   = (const int*)  d_in[0];
    const float* emb = (const float*)d_in[1];
    const float* W1  = (const float*)d_in[2];
    const float* b1  = (const float*)d_in[3];
    const float* W2  = (const float*)d_in[4];
    const float* b2  = (const float*)d_in[5];
    const float* W3  = (const float*)d_in[6];
    const float* b3  = (const float*)d_in[7];
    float* out = (float*)d_out;

    f16 *h0, *h1, *h2;
    f16 *w1hi, *w1lo, *w2hi, *w2lo, *w3hi, *w3lo;
    cudaGetSymbolAddress((void**)&h0, g_h0);
    cudaGetSymbolAddress((void**)&h1, g_h1);
    cudaGetSymbolAddress((void**)&h2, g_h2);
    cudaGetSymbolAddress((void**)&w1hi, g_W1hi);
    cudaGetSymbolAddress((void**)&w1lo, g_W1lo);
    cudaGetSymbolAddress((void**)&w2hi, g_W2hi);
    cudaGetSymbolAddress((void**)&w2lo, g_W2lo);
    cudaGetSymbolAddress((void**)&w3hi, g_W3hi);
    cudaGetSymbolAddress((void**)&w3lo, g_W3lo);

    cudaFuncSetAttribute(mma_gemm_kernel<1>,
                         cudaFuncAttributeMaxDynamicSharedMemorySize, SMEM_TOTAL);
    cudaFuncSetAttribute(mma_gemm_kernel<2>,
                         cudaFuncAttributeMaxDynamicSharedMemorySize, SMEM_TOTAL);

    init_pairs_kernel<<<1, 512>>>();
    {
        dim3 blk(32, 8);
        convert_w_kernel<<<dim3(DH1 / 32, K1P / 32), blk>>>(W1, w1hi, w1lo, DIN, DH1, K1P, DH1);
        convert_w_kernel<<<dim3(DH2 / 32, DH1 / 32), blk>>>(W2, w2hi, w2lo, DH1, DH2, DH1, DH2);
        convert_w_kernel<<<dim3(N3P / 32, DH2 / 32), blk>>>(W3, w3hi, w3lo, DH2, DOUT, DH2, N3P);
    }

    build_features_kernel<<<BATCH, 256>>>(x, emb, h0);

    mma_gemm_kernel<1><<<dim3(DH1 / BN, BATCH / BM), 256, SMEM_TOTAL>>>(
        h0, w1hi, w1lo, b1, h1, nullptr, K1P, DH1, K1P / BKC);
    mma_gemm_kernel<1><<<dim3(DH2 / BN, BATCH / BM), 256, SMEM_TOTAL>>>(
        h1, w2hi, w2lo, b2, h2, nullptr, DH1, DH2, DH1 / BKC);
    mma_gemm_kernel<2><<<dim3(N3P / BN, BATCH / BM), 256, SMEM_TOTAL>>>(
        h2, w3hi, w3lo, b3, nullptr, out, DH2, 0, DH2 / BKC);
}

// round 7
// speedup vs baseline: 2.1425x; 1.3610x over previous
#include <cuda_runtime.h>
#include <cuda_fp16.h>
#include <cstdint>

#define BATCH 8192
#define NFEAT 32
#define EDIM  64
#define VOCAB 1000
#define NPAIR 496
#define DIN   2544
#define K1P   2560
#define DH1   1024
#define DH2   512
#define DOUT  1000
#define N3P   1024

typedef __half f16;

// ---------------- scratch (device globals; no runtime allocation) ----------
__device__ f16 g_h0[(size_t)BATCH * K1P];
__device__ f16 g_h1[(size_t)BATCH * DH1];
__device__ f16 g_h2[(size_t)BATCH * DH2];
__device__ f16 g_W1[(size_t)DH1 * K1P];
__device__ f16 g_W2[(size_t)DH2 * DH1];
__device__ f16 g_W3[(size_t)N3P * DH2];
__device__ int g_pairs[NPAIR];

// ---------------- helpers ---------------------------------------------------
__device__ __forceinline__ uint32_t smem_u32(const void* p) {
    return (uint32_t)__cvta_generic_to_shared(p);
}
__device__ __forceinline__ void cp_async16(uint32_t dst, const void* src) {
    asm volatile("cp.async.cg.shared.global [%0], [%1], 16;\n" :: "r"(dst), "l"(src));
}
__device__ __forceinline__ void ldsm4(uint32_t addr, uint32_t& r0, uint32_t& r1,
                                      uint32_t& r2, uint32_t& r3) {
    asm volatile("ldmatrix.sync.aligned.m8n8.x4.shared.b16 {%0,%1,%2,%3}, [%4];\n"
                 : "=r"(r0), "=r"(r1), "=r"(r2), "=r"(r3) : "r"(addr));
}
__device__ __forceinline__ void mma_fp16(float c[4], const uint32_t a[4],
                                         uint32_t b0, uint32_t b1) {
    asm volatile("mma.sync.aligned.m16n8k16.row.col.f32.f16.f16.f32 "
                 "{%0,%1,%2,%3},{%4,%5,%6,%7},{%8,%9},{%0,%1,%2,%3};\n"
                 : "+f"(c[0]), "+f"(c[1]), "+f"(c[2]), "+f"(c[3])
                 : "r"(a[0]), "r"(a[1]), "r"(a[2]), "r"(a[3]), "r"(b0), "r"(b1));
}

// ---------------------------------------------------------------------------
__global__ void init_pairs_kernel() {
    const int p = threadIdx.x;
    if (p < NPAIR) {
        int i = 0, s = 0;
        while (p >= s + (NFEAT - 1 - i)) { s += NFEAT - 1 - i; i++; }
        g_pairs[p] = (i << 8) | (i + 1 + (p - s));
    }
}

// ---------------------------------------------------------------------------
// Weight conversion: W[K][N] fp32 -> transposed fp16 [Npad][Kpad], zero pad
// ---------------------------------------------------------------------------
__global__ void convert_w_kernel(const float* __restrict__ W,
                                 f16* __restrict__ hi,
                                 int K, int N, int Kpad, int Npad) {
    __shared__ float t[32][33];
    const int n0 = blockIdx.x * 32;
    const int k0 = blockIdx.y * 32;
    for (int r = threadIdx.y; r < 32; r += 8) {
        int k = k0 + r, n = n0 + threadIdx.x;
        t[r][threadIdx.x] = (k < K && n < N) ? W[(size_t)k * N + n] : 0.f;
    }
    __syncthreads();
    for (int r = threadIdx.y; r < 32; r += 8) {
        int n = n0 + r, k = k0 + threadIdx.x;
        if (n < Npad && k < Kpad)
            hi[(size_t)n * Kpad + k] = __float2half_rn(t[threadIdx.x][r]);
    }
}

// ---------------------------------------------------------------------------
// Feature build: gather + pairwise dots -> fp16 (padded to K1P)
// ---------------------------------------------------------------------------
__global__ __launch_bounds__(256)
void build_features_kernel(const int* __restrict__ x,
                           const float* __restrict__ emb,
                           f16* __restrict__ h0) {
    __shared__ float e[NFEAT][68];     // float4-aligned row stride
    __shared__ int idx[NFEAT];
    const int b = blockIdx.x;
    const int t = threadIdx.x;
    if (t < NFEAT) idx[t] = x[b * NFEAT + t];
    __syncthreads();

    const size_t base = (size_t)b * K1P;

    {   // gather: 8 threads per feature, 8 elems per thread, float4 loads
        const int f = t >> 3, d0 = (t & 7) * 8;
        const float* src = emb + ((size_t)f * VOCAB + idx[f]) * EDIM + d0;
        const float4 v0 = *(const float4*)src;
        const float4 v1 = *(const float4*)(src + 4);
        *(float4*)&e[f][d0]     = v0;
        *(float4*)&e[f][d0 + 4] = v1;

        __half2 ph[4];
        ph[0] = __floats2half2_rn(v0.x, v0.y);
        ph[1] = __floats2half2_rn(v0.z, v0.w);
        ph[2] = __floats2half2_rn(v1.x, v1.y);
        ph[3] = __floats2half2_rn(v1.z, v1.w);
        *(uint4*)(h0 + base + f * EDIM + d0) = *(uint4*)ph;
    }
    __syncthreads();

    for (int p = t; p < NPAIR; p += 256) {
        const int pr = g_pairs[p];
        const int i = pr >> 8, j = pr & 255;
        float sum = 0.f;
        #pragma unroll
        for (int d = 0; d < EDIM; d += 4) {
            const float4 a = *(const float4*)&e[i][d];
            const float4 c = *(const float4*)&e[j][d];
            sum += a.x * c.x + a.y * c.y + a.z * c.z + a.w * c.w;
        }
        h0[base + NFEAT * EDIM + p] = __float2half_rn(sum);
    }
    if (t < K1P - DIN) h0[base + DIN + t] = __float2half(0.f);
}

// ---------------------------------------------------------------------------
// fp16 tensor-core GEMM: C[M,N] = act( A @ B^T + bias ), fp32 accumulate
//   A: fp16 [M,Kp] K-major;  B: fp16 [Npad,Kp] K-major (W^T)
// BM=128, BN=64, BK=32; 256 threads, warps 4(m) x 2(n), warp tile 32x32.
// 3-stage cp.async ring; 2 CTAs/SM.
// ---------------------------------------------------------------------------
#define BM 128
#define BN 64
#define BKC 32
#define SPAD 40                           // halfs per row = 80B (16B-aligned)
#define A_BYTES (BM * SPAD * 2)           // 10240
#define B_BYTES (BN * SPAD * 2)           // 5120
#define STAGE_BYTES (A_BYTES + B_BYTES)   // 15360
#define NSTAGE 3
#define SMEM_TOTAL (NSTAGE * STAGE_BYTES) // 46080

template<int ACT>
__global__ __launch_bounds__(256, 2)
void mma_gemm_kernel(const f16* __restrict__ A, const f16* __restrict__ B,
                     const float* __restrict__ bias,
                     f16* __restrict__ Ch, float* __restrict__ Cf,
                     int Kp, int ldc, int nchunk) {
    extern __shared__ __align__(16) char smem[];

    const int tid  = threadIdx.x;
    const int lane = tid & 31;
    const int wid  = tid >> 5;
    const int wm   = (wid >> 1) * 32;
    const int wn   = (wid & 1) * 32;
    const int row0 = blockIdx.y * BM;
    const int col0 = blockIdx.x * BN;

    const int la_row = lane & 15;
    const int la_col = (lane >> 4) << 3;
    const int lb_row = (lane & 7) + ((lane >> 4) << 3);
    const int lb_col = ((lane >> 3) & 1) << 3;

    float acc[2][4][4];
    #pragma unroll
    for (int mi = 0; mi < 2; mi++)
        #pragma unroll
        for (int nb = 0; nb < 4; nb++)
            #pragma unroll
            for (int q = 0; q < 4; q++) acc[mi][nb][q] = 0.f;

    auto load_stage = [&](int s, int kc) {
        char* st = smem + s * STAGE_BYTES;
        const int k0 = kc * BKC;
        #pragma unroll
        for (int p = 0; p < 2; p++) {          // A: 128 rows x 4 segs
            const int c = tid + p * 256;
            const int r = c >> 2, sg = c & 3;
            const uint32_t so = (uint32_t)(r * (SPAD * 2) + sg * 16);
            const size_t g = (size_t)(row0 + r) * Kp + k0 + sg * 8;
            cp_async16(smem_u32(st + so), A + g);
        }
        {                                       // B: 64 rows x 4 segs
            const int r = tid >> 2, sg = tid & 3;
            const uint32_t so = (uint32_t)(r * (SPAD * 2) + sg * 16);
            const size_t g = (size_t)(col0 + r) * Kp + k0 + sg * 8;
            cp_async16(smem_u32(st + A_BYTES + so), B + g);
        }
        asm volatile("cp.async.commit_group;\n" ::: "memory");
    };

    load_stage(0, 0);
    load_stage(1, 1);

    for (int i = 0; i < nchunk; i++) {
        if (i + 2 < nchunk) {
            load_stage((i + 2) % NSTAGE, i + 2);
            asm volatile("cp.async.wait_group 2;\n" ::: "memory");
        } else if (i + 2 == nchunk) {
            asm volatile("cp.async.wait_group 1;\n" ::: "memory");
        } else {
            asm volatile("cp.async.wait_group 0;\n" ::: "memory");
        }
        __syncthreads();

        const char* st = smem + (i % NSTAGE) * STAGE_BYTES;
        const uint32_t sA = smem_u32(st);
        const uint32_t sB = sA + A_BYTES;

        #pragma unroll
        for (int ks = 0; ks < BKC; ks += 16) {
            uint32_t ar[2][4], br[2][4];
            #pragma unroll
            for (int mi = 0; mi < 2; mi++) {
                const uint32_t off =
                    (uint32_t)(((wm + mi * 16 + la_row) * SPAD + ks + la_col) * 2);
                ldsm4(sA + off, ar[mi][0], ar[mi][1], ar[mi][2], ar[mi][3]);
            }
            #pragma unroll
            for (int np = 0; np < 2; np++) {
                const uint32_t off =
                    (uint32_t)(((wn + np * 16 + lb_row) * SPAD + ks + lb_col) * 2);
                ldsm4(sB + off, br[np][0], br[np][1], br[np][2], br[np][3]);
            }
            #pragma unroll
            for (int mi = 0; mi < 2; mi++) {
                #pragma unroll
                for (int nb = 0; nb < 4; nb++) {
                    mma_fp16(acc[mi][nb], ar[mi],
                             br[nb >> 1][(nb & 1) * 2],
                             br[nb >> 1][(nb & 1) * 2 + 1]);
                }
            }
        }
        __syncthreads();
    }

    // -------- epilogue --------
    #pragma unroll
    for (int mi = 0; mi < 2; mi++) {
        #pragma unroll
        for (int nb = 0; nb < 4; nb++) {
            const int rg = row0 + wm + mi * 16 + (lane >> 2);
            const int cg = col0 + wn + nb * 8 + (lane & 3) * 2;
            float b0 = 0.f, b1 = 0.f;
            if (ACT == 2) {
                if (cg < DOUT)     b0 = bias[cg];
                if (cg + 1 < DOUT) b1 = bias[cg + 1];
            } else {
                b0 = bias[cg];
                b1 = bias[cg + 1];
            }
            const float* a = acc[mi][nb];
            #pragma unroll
            for (int h = 0; h < 2; h++) {
                const int r = rg + h * 8;
                float v0 = a[h * 2 + 0] + b0;
                float v1 = a[h * 2 + 1] + b1;
                if (ACT == 1) {
                    v0 = fmaxf(v0, 0.f);
                    v1 = fmaxf(v1, 0.f);
                    *(__half2*)(Ch + (size_t)r * ldc + cg) = __floats2half2_rn(v0, v1);
                } else {
                    if (cg + 2 <= DOUT) {
                        float2 o;
                        o.x = 1.f / (1.f + __expf(-v0));
                        o.y = 1.f / (1.f + __expf(-v1));
                        *(float2*)(Cf + (size_t)r * DOUT + cg) = o;
                    }
                }
            }
        }
    }
}

// ---------------------------------------------------------------------------
extern "C" void kernel_launch(void* const* d_in, const int* in_sizes, int n_in,
                              void* d_out, int out_size) {
    const int*   x   = (const int*)  d_in[0];
    const float* emb = (const float*)d_in[1];
    const float* W1  = (const float*)d_in[2];
    const float* b1  = (const float*)d_in[3];
    const float* W2  = (const float*)d_in[4];
    const float* b2  = (const float*)d_in[5];
    const float* W3  = (const float*)d_in[6];
    const float* b3  = (const float*)d_in[7];
    float* out = (float*)d_out;

    f16 *h0, *h1, *h2, *w1, *w2, *w3;
    cudaGetSymbolAddress((void**)&h0, g_h0);
    cudaGetSymbolAddress((void**)&h1, g_h1);
    cudaGetSymbolAddress((void**)&h2, g_h2);
    cudaGetSymbolAddress((void**)&w1, g_W1);
    cudaGetSymbolAddress((void**)&w2, g_W2);
    cudaGetSymbolAddress((void**)&w3, g_W3);

    cudaFuncSetAttribute(mma_gemm_kernel<1>,
                         cudaFuncAttributeMaxDynamicSharedMemorySize, SMEM_TOTAL);
    cudaFuncSetAttribute(mma_gemm_kernel<2>,
                         cudaFuncAttributeMaxDynamicSharedMemorySize, SMEM_TOTAL);

    init_pairs_kernel<<<1, 512>>>();
    {
        dim3 blk(32, 8);
        convert_w_kernel<<<dim3(DH1 / 32, K1P / 32), blk>>>(W1, w1, DIN, DH1, K1P, DH1);
        convert_w_kernel<<<dim3(DH2 / 32, DH1 / 32), blk>>>(W2, w2, DH1, DH2, DH1, DH2);
        convert_w_kernel<<<dim3(N3P / 32, DH2 / 32), blk>>>(W3, w3, DH2, DOUT, DH2, N3P);
    }

    build_features_kernel<<<BATCH, 256>>>(x, emb, h0);

    mma_gemm_kernel<1><<<dim3(DH1 / BN, BATCH / BM), 256, SMEM_TOTAL>>>(
        h0, w1, b1, h1, nullptr, K1P, DH1, K1P / BKC);
    mma_gemm_kernel<1><<<dim3(DH2 / BN, BATCH / BM), 256, SMEM_TOTAL>>>(
        h1, w2, b2, h2, nullptr, DH1, DH2, DH1 / BKC);
    mma_gemm_kernel<2><<<dim3(N3P / BN, BATCH / BM), 256, SMEM_TOTAL>>>(
        h2, w3, b3, nullptr, out, DH2, 0, DH2 / BKC);
}

// round 8
// speedup vs baseline: 2.2590x; 1.0544x over previous
#include <cuda_runtime.h>
#include <cuda_fp16.h>
#include <cstdint>

#define BATCH 8192
#define NFEAT 32
#define EDIM  64
#define VOCAB 1000
#define NPAIR 496
#define DIN   2544
#define K1P   2560
#define DH1   1024
#define DH2   512
#define DOUT  1000
#define N3P   1024

typedef __half f16;

// ---------------- scratch (device globals; no runtime allocation) ----------
__device__ f16 g_h0[(size_t)BATCH * K1P];
__device__ f16 g_h1[(size_t)BATCH * DH1];
__device__ f16 g_h2[(size_t)BATCH * DH2];
__device__ f16 g_W1[(size_t)DH1 * K1P];
__device__ f16 g_W2[(size_t)DH2 * DH1];
__device__ f16 g_W3[(size_t)N3P * DH2];
__device__ int g_pairs[NPAIR];

// ---------------- helpers ---------------------------------------------------
__device__ __forceinline__ uint32_t smem_u32(const void* p) {
    return (uint32_t)__cvta_generic_to_shared(p);
}
__device__ __forceinline__ void cp_async16(uint32_t dst, const void* src) {
    asm volatile("cp.async.cg.shared.global [%0], [%1], 16;\n" :: "r"(dst), "l"(src));
}
__device__ __forceinline__ void ldsm4(uint32_t addr, uint32_t& r0, uint32_t& r1,
                                      uint32_t& r2, uint32_t& r3) {
    asm volatile("ldmatrix.sync.aligned.m8n8.x4.shared.b16 {%0,%1,%2,%3}, [%4];\n"
                 : "=r"(r0), "=r"(r1), "=r"(r2), "=r"(r3) : "r"(addr));
}
__device__ __forceinline__ void mma_fp16(float c[4], const uint32_t a[4],
                                         uint32_t b0, uint32_t b1) {
    asm volatile("mma.sync.aligned.m16n8k16.row.col.f32.f16.f16.f32 "
                 "{%0,%1,%2,%3},{%4,%5,%6,%7},{%8,%9},{%0,%1,%2,%3};\n"
                 : "+f"(c[0]), "+f"(c[1]), "+f"(c[2]), "+f"(c[3])
                 : "r"(a[0]), "r"(a[1]), "r"(a[2]), "r"(a[3]), "r"(b0), "r"(b1));
}

// ---------------------------------------------------------------------------
__global__ void init_pairs_kernel() {
    const int p = threadIdx.x;
    if (p < NPAIR) {
        int i = 0, s = 0;
        while (p >= s + (NFEAT - 1 - i)) { s += NFEAT - 1 - i; i++; }
        g_pairs[p] = (i << 8) | (i + 1 + (p - s));
    }
}

// ---------------------------------------------------------------------------
// Weight conversion: W[K][N] fp32 -> transposed fp16 [Npad][Kpad], zero pad
// ---------------------------------------------------------------------------
__global__ void convert_w_kernel(const float* __restrict__ W,
                                 f16* __restrict__ hi,
                                 int K, int N, int Kpad, int Npad) {
    __shared__ float t[32][33];
    const int n0 = blockIdx.x * 32;
    const int k0 = blockIdx.y * 32;
    for (int r = threadIdx.y; r < 32; r += 8) {
        int k = k0 + r, n = n0 + threadIdx.x;
        t[r][threadIdx.x] = (k < K && n < N) ? W[(size_t)k * N + n] : 0.f;
    }
    __syncthreads();
    for (int r = threadIdx.y; r < 32; r += 8) {
        int n = n0 + r, k = k0 + threadIdx.x;
        if (n < Npad && k < Kpad)
            hi[(size_t)n * Kpad + k] = __float2half_rn(t[threadIdx.x][r]);
    }
}

// ---------------------------------------------------------------------------
// Feature build v2: gram via tensor cores.
// 8 warps/block, 1 sample per warp. Per warp:
//   load e (32x64 fp32) -> fp16 smem (stride 72) + write h0 emb part
//   gram = e @ e^T via 32 HMMAs -> fp16 smem (stride 36)
//   extract 496 upper-triangle pairs -> h0
// ---------------------------------------------------------------------------
#define FB_E_STRIDE 72                              // halfs, 144B rows
#define FB_WARP_BYTES (32 * FB_E_STRIDE * 2 + 32 * 36 * 2)   // 4608 + 2304 = 6912
#define FB_SMEM (8 * FB_WARP_BYTES)                 // 55296

__global__ __launch_bounds__(256)
void build_features_kernel(const int* __restrict__ x,
                           const float* __restrict__ emb,
                           f16* __restrict__ h0) {
    extern __shared__ __align__(16) char fsm[];
    const int tid  = threadIdx.x;
    const int wid  = tid >> 5;
    const int lane = tid & 31;
    const int b    = blockIdx.x * 8 + wid;

    f16* e_s    = (f16*)(fsm + wid * FB_WARP_BYTES);
    f16* gram_s = e_s + 32 * FB_E_STRIDE;

    const size_t base = (size_t)b * K1P;

    // each lane owns feature row f = lane: load 64 fp32, convert, store smem + h0
    {
        const int f = lane;
        const int myidx = x[b * NFEAT + f];
        const float* src = emb + ((size_t)f * VOCAB + myidx) * EDIM;
        uint4 ob[8];
        #pragma unroll
        for (int q = 0; q < 8; q++) {
            const float4 v0 = *(const float4*)(src + q * 8);
            const float4 v1 = *(const float4*)(src + q * 8 + 4);
            __half2 p0 = __floats2half2_rn(v0.x, v0.y);
            __half2 p1 = __floats2half2_rn(v0.z, v0.w);
            __half2 p2 = __floats2half2_rn(v1.x, v1.y);
            __half2 p3 = __floats2half2_rn(v1.z, v1.w);
            ob[q] = make_uint4(*(uint32_t*)&p0, *(uint32_t*)&p1,
                               *(uint32_t*)&p2, *(uint32_t*)&p3);
            *(uint4*)(e_s + f * FB_E_STRIDE + q * 8) = ob[q];
        }
        #pragma unroll
        for (int q = 0; q < 8; q++)
            *(uint4*)(h0 + base + f * EDIM + q * 8) = ob[q];
    }
    __syncwarp();

    // gram = e @ e^T : m=32 (2 tiles), n=32 (4 n8 tiles), k=64 (4 steps)
    {
        const int la_row = lane & 15;
        const int la_col = (lane >> 4) << 3;
        const int lb_row = (lane & 7) + ((lane >> 4) << 3);
        const int lb_col = ((lane >> 3) & 1) << 3;

        float acc[2][4][4];
        #pragma unroll
        for (int mi = 0; mi < 2; mi++)
            #pragma unroll
            for (int nb = 0; nb < 4; nb++)
                #pragma unroll
                for (int q = 0; q < 4; q++) acc[mi][nb][q] = 0.f;

        #pragma unroll
        for (int ks = 0; ks < EDIM; ks += 16) {
            uint32_t ar[2][4], br[2][4];
            #pragma unroll
            for (int mi = 0; mi < 2; mi++) {
                const uint32_t off = (uint32_t)(((mi * 16 + la_row) * FB_E_STRIDE
                                                 + ks + la_col) * 2);
                ldsm4(smem_u32(e_s) + off, ar[mi][0], ar[mi][1], ar[mi][2], ar[mi][3]);
            }
            #pragma unroll
            for (int np = 0; np < 2; np++) {
                const uint32_t off = (uint32_t)(((np * 16 + lb_row) * FB_E_STRIDE
                                                 + ks + lb_col) * 2);
                ldsm4(smem_u32(e_s) + off, br[np][0], br[np][1], br[np][2], br[np][3]);
            }
            #pragma unroll
            for (int mi = 0; mi < 2; mi++)
                #pragma unroll
                for (int nb = 0; nb < 4; nb++)
                    mma_fp16(acc[mi][nb], ar[mi],
                             br[nb >> 1][(nb & 1) * 2],
                             br[nb >> 1][(nb & 1) * 2 + 1]);
        }

        // store gram (fp16) to smem
        #pragma unroll
        for (int mi = 0; mi < 2; mi++) {
            #pragma unroll
            for (int nb = 0; nb < 4; nb++) {
                const int r0 = mi * 16 + (lane >> 2);
                const int c0 = nb * 8 + (lane & 3) * 2;
                *(__half2*)(gram_s + r0 * 36 + c0) =
                    __floats2half2_rn(acc[mi][nb][0], acc[mi][nb][1]);
                *(__half2*)(gram_s + (r0 + 8) * 36 + c0) =
                    __floats2half2_rn(acc[mi][nb][2], acc[mi][nb][3]);
            }
        }
    }
    __syncwarp();

    // extract upper triangle -> h0 cross features
    for (int p = lane; p < NPAIR; p += 32) {
        const int pr = g_pairs[p];
        h0[base + NFEAT * EDIM + p] = gram_s[(pr >> 8) * 36 + (pr & 255)];
    }
    if (lane < K1P - DIN) h0[base + DIN + lane] = __float2half(0.f);
}

// ---------------------------------------------------------------------------
// fp16 tensor-core GEMM: C[M,N] = act( A @ B^T + bias ), fp32 accumulate
// BMT=256: warp tile 64x32 (layer 1).  BMT=128: warp tile 32x32 (layers 2,3).
// BN=64, BK=32; 256 threads, warps 4(m) x 2(n); 3-stage cp.async; 2 CTAs/SM.
// ---------------------------------------------------------------------------
#define BN 64
#define BKC 32
#define SPAD 40                           // halfs per row = 80B (16B-aligned)
#define B_BYTES (BN * SPAD * 2)           // 5120

template<int ACT, int BMT>
__global__ __launch_bounds__(256, 2)
void mma_gemm_kernel(const f16* __restrict__ A, const f16* __restrict__ B,
                     const float* __restrict__ bias,
                     f16* __restrict__ Ch, float* __restrict__ Cf,
                     int Kp, int ldc, int nchunk) {
    constexpr int MI = BMT / 64;                       // m16-tiles per warp
    constexpr int A_BYTES = BMT * SPAD * 2;
    constexpr int STAGE_BYTES = A_BYTES + B_BYTES;
    extern __shared__ __align__(16) char smem[];

    const int tid  = threadIdx.x;
    const int lane = tid & 31;
    const int wid  = tid >> 5;
    const int wm   = (wid >> 1) * (MI * 16);
    const int wn   = (wid & 1) * 32;
    const int row0 = blockIdx.y * BMT;
    const int col0 = blockIdx.x * BN;

    const int la_row = lane & 15;
    const int la_col = (lane >> 4) << 3;
    const int lb_row = (lane & 7) + ((lane >> 4) << 3);
    const int lb_col = ((lane >> 3) & 1) << 3;

    float acc[MI][4][4];
    #pragma unroll
    for (int mi = 0; mi < MI; mi++)
        #pragma unroll
        for (int nb = 0; nb < 4; nb++)
            #pragma unroll
            for (int q = 0; q < 4; q++) acc[mi][nb][q] = 0.f;

    auto load_stage = [&](int s, int kc) {
        char* st = smem + s * STAGE_BYTES;
        const int k0 = kc * BKC;
        #pragma unroll
        for (int p = 0; p < BMT / 64; p++) {   // A: BMT rows x 4 segs
            const int c = tid + p * 256;
            const int r = c >> 2, sg = c & 3;
            const uint32_t so = (uint32_t)(r * (SPAD * 2) + sg * 16);
            const size_t g = (size_t)(row0 + r) * Kp + k0 + sg * 8;
            cp_async16(smem_u32(st + so), A + g);
        }
        {                                       // B: 64 rows x 4 segs
            const int r = tid >> 2, sg = tid & 3;
            const uint32_t so = (uint32_t)(r * (SPAD * 2) + sg * 16);
            const size_t g = (size_t)(col0 + r) * Kp + k0 + sg * 8;
            cp_async16(smem_u32(st + A_BYTES + so), B + g);
        }
        asm volatile("cp.async.commit_group;\n" ::: "memory");
    };

    load_stage(0, 0);
    load_stage(1, 1);

    for (int i = 0; i < nchunk; i++) {
        if (i + 2 < nchunk) {
            load_stage((i + 2) % 3, i + 2);
            asm volatile("cp.async.wait_group 2;\n" ::: "memory");
        } else if (i + 2 == nchunk) {
            asm volatile("cp.async.wait_group 1;\n" ::: "memory");
        } else {
            asm volatile("cp.async.wait_group 0;\n" ::: "memory");
        }
        __syncthreads();

        const char* st = smem + (i % 3) * STAGE_BYTES;
        const uint32_t sA = smem_u32(st);
        const uint32_t sB = sA + A_BYTES;

        #pragma unroll
        for (int ks = 0; ks < BKC; ks += 16) {
            uint32_t ar[MI][4], br[2][4];
            #pragma unroll
            for (int mi = 0; mi < MI; mi++) {
                const uint32_t off =
                    (uint32_t)(((wm + mi * 16 + la_row) * SPAD + ks + la_col) * 2);
                ldsm4(sA + off, ar[mi][0], ar[mi][1], ar[mi][2], ar[mi][3]);
            }
            #pragma unroll
            for (int np = 0; np < 2; np++) {
                const uint32_t off =
                    (uint32_t)(((wn + np * 16 + lb_row) * SPAD + ks + lb_col) * 2);
                ldsm4(sB + off, br[np][0], br[np][1], br[np][2], br[np][3]);
            }
            #pragma unroll
            for (int mi = 0; mi < MI; mi++) {
                #pragma unroll
                for (int nb = 0; nb < 4; nb++) {
                    mma_fp16(acc[mi][nb], ar[mi],
                             br[nb >> 1][(nb & 1) * 2],
                             br[nb >> 1][(nb & 1) * 2 + 1]);
                }
            }
        }
        __syncthreads();
    }

    // -------- epilogue --------
    #pragma unroll
    for (int mi = 0; mi < MI; mi++) {
        #pragma unroll
        for (int nb = 0; nb < 4; nb++) {
            const int rg = row0 + wm + mi * 16 + (lane >> 2);
            const int cg = col0 + wn + nb * 8 + (lane & 3) * 2;
            float b0 = 0.f, b1 = 0.f;
            if (ACT == 2) {
                if (cg < DOUT)     b0 = bias[cg];
                if (cg + 1 < DOUT) b1 = bias[cg + 1];
            } else {
                b0 = bias[cg];
                b1 = bias[cg + 1];
            }
            const float* a = acc[mi][nb];
            #pragma unroll
            for (int h = 0; h < 2; h++) {
                const int r = rg + h * 8;
                float v0 = a[h * 2 + 0] + b0;
                float v1 = a[h * 2 + 1] + b1;
                if (ACT == 1) {
                    v0 = fmaxf(v0, 0.f);
                    v1 = fmaxf(v1, 0.f);
                    *(__half2*)(Ch + (size_t)r * ldc + cg) = __floats2half2_rn(v0, v1);
                } else {
                    if (cg + 2 <= DOUT) {
                        float2 o;
                        o.x = 1.f / (1.f + __expf(-v0));
                        o.y = 1.f / (1.f + __expf(-v1));
                        *(float2*)(Cf + (size_t)r * DOUT + cg) = o;
                    }
                }
            }
        }
    }
}

// ---------------------------------------------------------------------------
extern "C" void kernel_launch(void* const* d_in, const int* in_sizes, int n_in,
                              void* d_out, int out_size) {
    const int*   x   = (const int*)  d_in[0];
    const float* emb = (const float*)d_in[1];
    const float* W1  = (const float*)d_in[2];
    const float* b1  = (const float*)d_in[3];
    const float* W2  = (const float*)d_in[4];
    const float* b2  = (const float*)d_in[5];
    const float* W3  = (const float*)d_in[6];
    const float* b3  = (const float*)d_in[7];
    float* out = (float*)d_out;

    f16 *h0, *h1, *h2, *w1, *w2, *w3;
    cudaGetSymbolAddress((void**)&h0, g_h0);
    cudaGetSymbolAddress((void**)&h1, g_h1);
    cudaGetSymbolAddress((void**)&h2, g_h2);
    cudaGetSymbolAddress((void**)&w1, g_W1);
    cudaGetSymbolAddress((void**)&w2, g_W2);
    cudaGetSymbolAddress((void**)&w3, g_W3);

    const int smem256 = 3 * (256 * SPAD * 2 + B_BYTES);   // 76800
    const int smem128 = 3 * (128 * SPAD * 2 + B_BYTES);   // 46080
    cudaFuncSetAttribute((const void*)mma_gemm_kernel<1, 256>,
                         cudaFuncAttributeMaxDynamicSharedMemorySize, smem256);
    cudaFuncSetAttribute((const void*)mma_gemm_kernel<1, 128>,
                         cudaFuncAttributeMaxDynamicSharedMemorySize, smem128);
    cudaFuncSetAttribute((const void*)mma_gemm_kernel<2, 128>,
                         cudaFuncAttributeMaxDynamicSharedMemorySize, smem128);
    cudaFuncSetAttribute((const void*)build_features_kernel,
                         cudaFuncAttributeMaxDynamicSharedMemorySize, FB_SMEM);

    init_pairs_kernel<<<1, 512>>>();
    {
        dim3 blk(32, 8);
        convert_w_kernel<<<dim3(DH1 / 32, K1P / 32), blk>>>(W1, w1, DIN, DH1, K1P, DH1);
        convert_w_kernel<<<dim3(DH2 / 32, DH1 / 32), blk>>>(W2, w2, DH1, DH2, DH1, DH2);
        convert_w_kernel<<<dim3(N3P / 32, DH2 / 32), blk>>>(W3, w3, DH2, DOUT, DH2, N3P);
    }

    build_features_kernel<<<BATCH / 8, 256, FB_SMEM>>>(x, emb, h0);

    mma_gemm_kernel<1, 256><<<dim3(DH1 / BN, BATCH / 256), 256, smem256>>>(
        h0, w1, b1, h1, nullptr, K1P, DH1, K1P / BKC);
    mma_gemm_kernel<1, 128><<<dim3(DH2 / BN, BATCH / 128), 256, smem128>>>(
        h1, w2, b2, h2, nullptr, DH1, DH2, DH1 / BKC);
    mma_gemm_kernel<2, 128><<<dim3(N3P / BN, BATCH / 128), 256, smem128>>>(
        h2, w3, b3, nullptr, out, DH2, 0, DH2 / BKC);
}

// round 9
// speedup vs baseline: 2.6029x; 1.1522x over previous
#include <cuda_runtime.h>
#include <cuda_fp16.h>
#include <cstdint>

#define BATCH 8192
#define NFEAT 32
#define EDIM  64
#define VOCAB 1000
#define NPAIR 496
#define DIN   2544
#define K1P   2560
#define DH1   1024
#define DH2   512
#define DOUT  1000
#define N3P   1024

typedef __half f16;

// ---------------- scratch (device globals; no runtime allocation) ----------
__device__ f16 g_h0[(size_t)BATCH * K1P];
__device__ f16 g_h1[(size_t)BATCH * DH1];
__device__ f16 g_h2[(size_t)BATCH * DH2];
__device__ f16 g_W1[(size_t)DH1 * K1P];
__device__ f16 g_W2[(size_t)DH2 * DH1];
__device__ f16 g_W3[(size_t)N3P * DH2];
__device__ int g_pairs[NPAIR];

// ---------------- helpers ---------------------------------------------------
__device__ __forceinline__ uint32_t smem_u32(const void* p) {
    return (uint32_t)__cvta_generic_to_shared(p);
}
__device__ __forceinline__ void cp_async16(uint32_t dst, const void* src) {
    asm volatile("cp.async.cg.shared.global [%0], [%1], 16;\n" :: "r"(dst), "l"(src));
}
__device__ __forceinline__ void ldsm4(uint32_t addr, uint32_t& r0, uint32_t& r1,
                                      uint32_t& r2, uint32_t& r3) {
    asm volatile("ldmatrix.sync.aligned.m8n8.x4.shared.b16 {%0,%1,%2,%3}, [%4];\n"
                 : "=r"(r0), "=r"(r1), "=r"(r2), "=r"(r3) : "r"(addr));
}
__device__ __forceinline__ void mma_fp16(float c[4], const uint32_t a[4],
                                         uint32_t b0, uint32_t b1) {
    asm volatile("mma.sync.aligned.m16n8k16.row.col.f32.f16.f16.f32 "
                 "{%0,%1,%2,%3},{%4,%5,%6,%7},{%8,%9},{%0,%1,%2,%3};\n"
                 : "+f"(c[0]), "+f"(c[1]), "+f"(c[2]), "+f"(c[3])
                 : "r"(a[0]), "r"(a[1]), "r"(a[2]), "r"(a[3]), "r"(b0), "r"(b1));
}

// ---------------------------------------------------------------------------
__global__ void init_pairs_kernel() {
    const int p = threadIdx.x;
    if (p < NPAIR) {
        int i = 0, s = 0;
        while (p >= s + (NFEAT - 1 - i)) { s += NFEAT - 1 - i; i++; }
        g_pairs[p] = (i << 8) | (i + 1 + (p - s));
    }
}

// ---------------------------------------------------------------------------
// Weight conversion: W[K][N] fp32 -> transposed fp16 [Npad][Kpad], zero pad
// ---------------------------------------------------------------------------
__global__ void convert_w_kernel(const float* __restrict__ W,
                                 f16* __restrict__ hi,
                                 int K, int N, int Kpad, int Npad) {
    __shared__ float t[32][33];
    const int n0 = blockIdx.x * 32;
    const int k0 = blockIdx.y * 32;
    for (int r = threadIdx.y; r < 32; r += 8) {
        int k = k0 + r, n = n0 + threadIdx.x;
        t[r][threadIdx.x] = (k < K && n < N) ? W[(size_t)k * N + n] : 0.f;
    }
    __syncthreads();
    for (int r = threadIdx.y; r < 32; r += 8) {
        int n = n0 + r, k = k0 + threadIdx.x;
        if (n < Npad && k < Kpad)
            hi[(size_t)n * Kpad + k] = __float2half_rn(t[threadIdx.x][r]);
    }
}

// ---------------------------------------------------------------------------
// Feature build: gram via tensor cores (1 sample per warp, 8 warps/block)
// ---------------------------------------------------------------------------
#define FB_E_STRIDE 72
#define FB_WARP_BYTES (32 * FB_E_STRIDE * 2 + 32 * 36 * 2)
#define FB_SMEM (8 * FB_WARP_BYTES)

__global__ __launch_bounds__(256)
void build_features_kernel(const int* __restrict__ x,
                           const float* __restrict__ emb,
                           f16* __restrict__ h0) {
    extern __shared__ __align__(16) char fsm[];
    const int tid  = threadIdx.x;
    const int wid  = tid >> 5;
    const int lane = tid & 31;
    const int b    = blockIdx.x * 8 + wid;

    f16* e_s    = (f16*)(fsm + wid * FB_WARP_BYTES);
    f16* gram_s = e_s + 32 * FB_E_STRIDE;

    const size_t base = (size_t)b * K1P;

    {
        const int f = lane;
        const int myidx = x[b * NFEAT + f];
        const float* src = emb + ((size_t)f * VOCAB + myidx) * EDIM;
        uint4 ob[8];
        #pragma unroll
        for (int q = 0; q < 8; q++) {
            const float4 v0 = *(const float4*)(src + q * 8);
            const float4 v1 = *(const float4*)(src + q * 8 + 4);
            __half2 p0 = __floats2half2_rn(v0.x, v0.y);
            __half2 p1 = __floats2half2_rn(v0.z, v0.w);
            __half2 p2 = __floats2half2_rn(v1.x, v1.y);
            __half2 p3 = __floats2half2_rn(v1.z, v1.w);
            ob[q] = make_uint4(*(uint32_t*)&p0, *(uint32_t*)&p1,
                               *(uint32_t*)&p2, *(uint32_t*)&p3);
            *(uint4*)(e_s + f * FB_E_STRIDE + q * 8) = ob[q];
        }
        #pragma unroll
        for (int q = 0; q < 8; q++)
            *(uint4*)(h0 + base + f * EDIM + q * 8) = ob[q];
    }
    __syncwarp();

    {
        const int la_row = lane & 15;
        const int la_col = (lane >> 4) << 3;
        const int lb_row = (lane & 7) + ((lane >> 4) << 3);
        const int lb_col = ((lane >> 3) & 1) << 3;

        float acc[2][4][4];
        #pragma unroll
        for (int mi = 0; mi < 2; mi++)
            #pragma unroll
            for (int nb = 0; nb < 4; nb++)
                #pragma unroll
                for (int q = 0; q < 4; q++) acc[mi][nb][q] = 0.f;

        #pragma unroll
        for (int ks = 0; ks < EDIM; ks += 16) {
            uint32_t ar[2][4], br[2][4];
            #pragma unroll
            for (int mi = 0; mi < 2; mi++) {
                const uint32_t off = (uint32_t)(((mi * 16 + la_row) * FB_E_STRIDE
                                                 + ks + la_col) * 2);
                ldsm4(smem_u32(e_s) + off, ar[mi][0], ar[mi][1], ar[mi][2], ar[mi][3]);
            }
            #pragma unroll
            for (int np = 0; np < 2; np++) {
                const uint32_t off = (uint32_t)(((np * 16 + lb_row) * FB_E_STRIDE
                                                 + ks + lb_col) * 2);
                ldsm4(smem_u32(e_s) + off, br[np][0], br[np][1], br[np][2], br[np][3]);
            }
            #pragma unroll
            for (int mi = 0; mi < 2; mi++)
                #pragma unroll
                for (int nb = 0; nb < 4; nb++)
                    mma_fp16(acc[mi][nb], ar[mi],
                             br[nb >> 1][(nb & 1) * 2],
                             br[nb >> 1][(nb & 1) * 2 + 1]);
        }

        #pragma unroll
        for (int mi = 0; mi < 2; mi++) {
            #pragma unroll
            for (int nb = 0; nb < 4; nb++) {
                const int r0 = mi * 16 + (lane >> 2);
                const int c0 = nb * 8 + (lane & 3) * 2;
                *(__half2*)(gram_s + r0 * 36 + c0) =
                    __floats2half2_rn(acc[mi][nb][0], acc[mi][nb][1]);
                *(__half2*)(gram_s + (r0 + 8) * 36 + c0) =
                    __floats2half2_rn(acc[mi][nb][2], acc[mi][nb][3]);
            }
        }
    }
    __syncwarp();

    for (int p = lane; p < NPAIR; p += 32) {
        const int pr = g_pairs[p];
        h0[base + NFEAT * EDIM + p] = gram_s[(pr >> 8) * 36 + (pr & 255)];
    }
    if (lane < K1P - DIN) h0[base + DIN + lane] = __float2half(0.f);
}

// ---------------------------------------------------------------------------
// fp16 tensor-core GEMM: C[M,N] = act( A @ B^T + bias ), fp32 accumulate
// BM=256, BN=64, BK=64; 256 threads, warps 4(m) x 2(n), warp tile 64x32.
// 2-stage cp.async ring; 2 CTAs/SM.
// ---------------------------------------------------------------------------
#define BM 256
#define BN 64
#define BKC 64
#define SPAD 72                           // halfs per row = 144B (16B-aligned)
#define A_BYTES (BM * SPAD * 2)           // 36864
#define B_BYTES (BN * SPAD * 2)           // 9216
#define STAGE_BYTES (A_BYTES + B_BYTES)   // 46080
#define SMEM_TOTAL (2 * STAGE_BYTES)      // 92160

template<int ACT>
__global__ __launch_bounds__(256, 2)
void mma_gemm_kernel(const f16* __restrict__ A, const f16* __restrict__ B,
                     const float* __restrict__ bias,
                     f16* __restrict__ Ch, float* __restrict__ Cf,
                     int Kp, int ldc, int nchunk) {
    extern __shared__ __align__(16) char smem[];

    const int tid  = threadIdx.x;
    const int lane = tid & 31;
    const int wid  = tid >> 5;
    const int wm   = (wid >> 1) * 64;
    const int wn   = (wid & 1) * 32;
    const int row0 = blockIdx.y * BM;
    const int col0 = blockIdx.x * BN;

    const int la_row = lane & 15;
    const int la_col = (lane >> 4) << 3;
    const int lb_row = (lane & 7) + ((lane >> 4) << 3);
    const int lb_col = ((lane >> 3) & 1) << 3;

    float acc[4][4][4];
    #pragma unroll
    for (int mi = 0; mi < 4; mi++)
        #pragma unroll
        for (int nb = 0; nb < 4; nb++)
            #pragma unroll
            for (int q = 0; q < 4; q++) acc[mi][nb][q] = 0.f;

    auto load_stage = [&](int s, int kc) {
        char* st = smem + s * STAGE_BYTES;
        const int k0 = kc * BKC;
        #pragma unroll
        for (int p = 0; p < 8; p++) {          // A: 256 rows x 8 segs
            const int c = tid + p * 256;
            const int r = c >> 3, sg = c & 7;
            const uint32_t so = (uint32_t)(r * (SPAD * 2) + sg * 16);
            const size_t g = (size_t)(row0 + r) * Kp + k0 + sg * 8;
            cp_async16(smem_u32(st + so), A + g);
        }
        #pragma unroll
        for (int p = 0; p < 2; p++) {          // B: 64 rows x 8 segs
            const int c = tid + p * 256;
            const int r = c >> 3, sg = c & 7;
            const uint32_t so = (uint32_t)(r * (SPAD * 2) + sg * 16);
            const size_t g = (size_t)(col0 + r) * Kp + k0 + sg * 8;
            cp_async16(smem_u32(st + A_BYTES + so), B + g);
        }
        asm volatile("cp.async.commit_group;\n" ::: "memory");
    };

    load_stage(0, 0);
    load_stage(1, 1);

    for (int i = 0; i < nchunk; i++) {
        if (i + 1 < nchunk) asm volatile("cp.async.wait_group 1;\n" ::: "memory");
        else                asm volatile("cp.async.wait_group 0;\n" ::: "memory");
        __syncthreads();

        const char* st = smem + (i & 1) * STAGE_BYTES;
        const uint32_t sA = smem_u32(st);
        const uint32_t sB = sA + A_BYTES;

        #pragma unroll
        for (int ks = 0; ks < BKC; ks += 16) {
            uint32_t ar[4][4], br[2][4];
            #pragma unroll
            for (int mi = 0; mi < 4; mi++) {
                const uint32_t off =
                    (uint32_t)(((wm + mi * 16 + la_row) * SPAD + ks + la_col) * 2);
                ldsm4(sA + off, ar[mi][0], ar[mi][1], ar[mi][2], ar[mi][3]);
            }
            #pragma unroll
            for (int np = 0; np < 2; np++) {
                const uint32_t off =
                    (uint32_t)(((wn + np * 16 + lb_row) * SPAD + ks + lb_col) * 2);
                ldsm4(sB + off, br[np][0], br[np][1], br[np][2], br[np][3]);
            }
            #pragma unroll
            for (int mi = 0; mi < 4; mi++) {
                #pragma unroll
                for (int nb = 0; nb < 4; nb++) {
                    mma_fp16(acc[mi][nb], ar[mi],
                             br[nb >> 1][(nb & 1) * 2],
                             br[nb >> 1][(nb & 1) * 2 + 1]);
                }
            }
        }
        __syncthreads();
        if (i + 2 < nchunk) load_stage(i & 1, i + 2);
    }

    // -------- epilogue --------
    #pragma unroll
    for (int mi = 0; mi < 4; mi++) {
        #pragma unroll
        for (int nb = 0; nb < 4; nb++) {
            const int rg = row0 + wm + mi * 16 + (lane >> 2);
            const int cg = col0 + wn + nb * 8 + (lane & 3) * 2;
            float b0 = 0.f, b1 = 0.f;
            if (ACT == 2) {
                if (cg < DOUT)     b0 = bias[cg];
                if (cg + 1 < DOUT) b1 = bias[cg + 1];
            } else {
                b0 = bias[cg];
                b1 = bias[cg + 1];
            }
            const float* a = acc[mi][nb];
            #pragma unroll
            for (int h = 0; h < 2; h++) {
                const int r = rg + h * 8;
                float v0 = a[h * 2 + 0] + b0;
                float v1 = a[h * 2 + 1] + b1;
                if (ACT == 1) {
                    v0 = fmaxf(v0, 0.f);
                    v1 = fmaxf(v1, 0.f);
                    *(__half2*)(Ch + (size_t)r * ldc + cg) = __floats2half2_rn(v0, v1);
                } else {
                    if (cg + 2 <= DOUT) {
                        float2 o;
                        o.x = 1.f / (1.f + __expf(-v0));
                        o.y = 1.f / (1.f + __expf(-v1));
                        *(float2*)(Cf + (size_t)r * DOUT + cg) = o;
                    }
                }
            }
        }
    }
}

// ---------------------------------------------------------------------------
extern "C" void kernel_launch(void* const* d_in, const int* in_sizes, int n_in,
                              void* d_out, int out_size) {
    const int*   x   = (const int*)  d_in[0];
    const float* emb = (const float*)d_in[1];
    const float* W1  = (const float*)d_in[2];
    const float* b1  = (const float*)d_in[3];
    const float* W2  = (const float*)d_in[4];
    const float* b2  = (const float*)d_in[5];
    const float* W3  = (const float*)d_in[6];
    const float* b3  = (const float*)d_in[7];
    float* out = (float*)d_out;

    f16 *h0, *h1, *h2, *w1, *w2, *w3;
    cudaGetSymbolAddress((void**)&h0, g_h0);
    cudaGetSymbolAddress((void**)&h1, g_h1);
    cudaGetSymbolAddress((void**)&h2, g_h2);
    cudaGetSymbolAddress((void**)&w1, g_W1);
    cudaGetSymbolAddress((void**)&w2, g_W2);
    cudaGetSymbolAddress((void**)&w3, g_W3);

    cudaFuncSetAttribute((const void*)mma_gemm_kernel<1>,
                         cudaFuncAttributeMaxDynamicSharedMemorySize, SMEM_TOTAL);
    cudaFuncSetAttribute((const void*)mma_gemm_kernel<2>,
                         cudaFuncAttributeMaxDynamicSharedMemorySize, SMEM_TOTAL);
    cudaFuncSetAttribute((const void*)build_features_kernel,
                         cudaFuncAttributeMaxDynamicSharedMemorySize, FB_SMEM);

    init_pairs_kernel<<<1, 512>>>();
    {
        dim3 blk(32, 8);
        convert_w_kernel<<<dim3(DH1 / 32, K1P / 32), blk>>>(W1, w1, DIN, DH1, K1P, DH1);
        convert_w_kernel<<<dim3(DH2 / 32, DH1 / 32), blk>>>(W2, w2, DH1, DH2, DH1, DH2);
        convert_w_kernel<<<dim3(N3P / 32, DH2 / 32), blk>>>(W3, w3, DH2, DOUT, DH2, N3P);
    }

    build_features_kernel<<<BATCH / 8, 256, FB_SMEM>>>(x, emb, h0);

    mma_gemm_kernel<1><<<dim3(DH1 / BN, BATCH / BM), 256, SMEM_TOTAL>>>(
        h0, w1, b1, h1, nullptr, K1P, DH1, K1P / BKC);
    mma_gemm_kernel<1><<<dim3(DH2 / BN, BATCH / BM), 256, SMEM_TOTAL>>>(
        h1, w2, b2, h2, nullptr, DH1, DH2, DH1 / BKC);
    mma_gemm_kernel<2><<<dim3(N3P / BN, BATCH / BM), 256, SMEM_TOTAL>>>(
        h2, w3, b3, nullptr, out, DH2, 0, DH2 / BKC);
}

// round 10
// speedup vs baseline: 2.6478x; 1.0172x over previous
#include <cuda_runtime.h>
#include <cuda_fp16.h>
#include <cstdint>

#define BATCH 8192
#define NFEAT 32
#define EDIM  64
#define VOCAB 1000
#define NPAIR 496
#define DIN   2544
#define K1P   2560
#define DH1   1024
#define DH2   512
#define DOUT  1000
#define N3P   1024

typedef __half f16;

// ---------------- scratch (device globals; no runtime allocation) ----------
__device__ f16 g_h0[(size_t)BATCH * K1P];
__device__ f16 g_h1[(size_t)BATCH * DH1];
__device__ f16 g_h2[(size_t)BATCH * DH2];
__device__ f16 g_W1[(size_t)DH1 * K1P];
__device__ f16 g_W2[(size_t)DH2 * DH1];
__device__ f16 g_W3[(size_t)N3P * DH2];

// ---------------- helpers ---------------------------------------------------
__device__ __forceinline__ uint32_t smem_u32(const void* p) {
    return (uint32_t)__cvta_generic_to_shared(p);
}
__device__ __forceinline__ void cp_async16(uint32_t dst, const void* src) {
    asm volatile("cp.async.cg.shared.global [%0], [%1], 16;\n" :: "r"(dst), "l"(src));
}
__device__ __forceinline__ void ldsm4(uint32_t addr, uint32_t& r0, uint32_t& r1,
                                      uint32_t& r2, uint32_t& r3) {
    asm volatile("ldmatrix.sync.aligned.m8n8.x4.shared.b16 {%0,%1,%2,%3}, [%4];\n"
                 : "=r"(r0), "=r"(r1), "=r"(r2), "=r"(r3) : "r"(addr));
}
__device__ __forceinline__ void mma_fp16(float c[4], const uint32_t a[4],
                                         uint32_t b0, uint32_t b1) {
    asm volatile("mma.sync.aligned.m16n8k16.row.col.f32.f16.f16.f32 "
                 "{%0,%1,%2,%3},{%4,%5,%6,%7},{%8,%9},{%0,%1,%2,%3};\n"
                 : "+f"(c[0]), "+f"(c[1]), "+f"(c[2]), "+f"(c[3])
                 : "r"(a[0]), "r"(a[1]), "r"(a[2]), "r"(a[3]), "r"(b0), "r"(b1));
}

// ---------------------------------------------------------------------------
// Fused prep kernel: weight converts + feature build, one launch.
// Block ranges:
//   [0, 2560)            : convert W1  (nbx=32,  K=DIN,  N=DH1, Kpad=K1P, Npad=DH1)
//   [2560, 3072)         : convert W2  (nbx=16,  K=DH1,  N=DH2, Kpad=DH1, Npad=DH2)
//   [3072, 3584)         : convert W3  (nbx=32,  K=DH2,  N=DOUT,Kpad=DH2, Npad=N3P)
//   [3584, 3584+1024)    : features (8 samples per block, 1 per warp)
// ---------------------------------------------------------------------------
#define CONV1_BLKS 2560
#define CONV2_BLKS 512
#define CONV3_BLKS 512
#define CONV_BLKS  (CONV1_BLKS + CONV2_BLKS + CONV3_BLKS)   // 3584
#define FEAT_BLKS  (BATCH / 8)                               // 1024
#define PREP_BLKS  (CONV_BLKS + FEAT_BLKS)                   // 4608

#define FB_E_STRIDE 72
#define FB_WARP_BYTES (32 * FB_E_STRIDE * 2 + 32 * 36 * 2)   // 6912
#define FB_PAIRS_BYTES 2048
#define PREP_SMEM (FB_PAIRS_BYTES + 8 * FB_WARP_BYTES)       // 57344

__device__ __forceinline__ void convert_body(char* sm,
                                             const float* __restrict__ W,
                                             f16* __restrict__ dst,
                                             int K, int N, int Kpad, int Npad,
                                             int cid, int nbx) {
    float (*t)[33] = (float(*)[33])sm;
    const int tx = threadIdx.x & 31;
    const int ty = threadIdx.x >> 5;           // 0..7
    const int n0 = (cid % nbx) * 32;
    const int k0 = (cid / nbx) * 32;
    for (int r = ty; r < 32; r += 8) {
        int k = k0 + r, n = n0 + tx;
        t[r][tx] = (k < K && n < N) ? W[(size_t)k * N + n] : 0.f;
    }
    __syncthreads();
    for (int r = ty; r < 32; r += 8) {
        int n = n0 + r, k = k0 + tx;
        if (n < Npad && k < Kpad)
            dst[(size_t)n * Kpad + k] = __float2half_rn(t[tx][r]);
    }
}

__global__ __launch_bounds__(256)
void prep_kernel(const int* __restrict__ x,
                 const float* __restrict__ emb,
                 const float* __restrict__ W1,
                 const float* __restrict__ W2,
                 const float* __restrict__ W3,
                 f16* __restrict__ w1, f16* __restrict__ w2, f16* __restrict__ w3,
                 f16* __restrict__ h0) {
    extern __shared__ __align__(16) char sm[];
    const int bid = blockIdx.x;

    if (bid < CONV1_BLKS) {
        convert_body(sm, W1, w1, DIN, DH1, K1P, DH1, bid, 32);
        return;
    }
    if (bid < CONV1_BLKS + CONV2_BLKS) {
        convert_body(sm, W2, w2, DH1, DH2, DH1, DH2, bid - CONV1_BLKS, 16);
        return;
    }
    if (bid < CONV_BLKS) {
        convert_body(sm, W3, w3, DH2, DOUT, DH2, N3P, bid - CONV1_BLKS - CONV2_BLKS, 32);
        return;
    }

    // ---------------- features ----------------
    const int fb   = bid - CONV_BLKS;
    const int tid  = threadIdx.x;
    const int wid  = tid >> 5;
    const int lane = tid & 31;
    const int b    = fb * 8 + wid;

    int* pairs_s = (int*)sm;
    f16* e_s    = (f16*)(sm + FB_PAIRS_BYTES + wid * FB_WARP_BYTES);
    f16* gram_s = e_s + 32 * FB_E_STRIDE;

    // build pair table in smem
    for (int p = tid; p < NPAIR; p += 256) {
        int i = 0, s = 0;
        while (p >= s + (NFEAT - 1 - i)) { s += NFEAT - 1 - i; i++; }
        pairs_s[p] = (i << 8) | (i + 1 + (p - s));
    }
    __syncthreads();

    const size_t base = (size_t)b * K1P;

    {   // lane f loads its 64-float embedding row, converts, stores smem + h0
        const int f = lane;
        const int myidx = x[b * NFEAT + f];
        const float* src = emb + ((size_t)f * VOCAB + myidx) * EDIM;
        uint4 ob[8];
        #pragma unroll
        for (int q = 0; q < 8; q++) {
            const float4 v0 = *(const float4*)(src + q * 8);
            const float4 v1 = *(const float4*)(src + q * 8 + 4);
            __half2 p0 = __floats2half2_rn(v0.x, v0.y);
            __half2 p1 = __floats2half2_rn(v0.z, v0.w);
            __half2 p2 = __floats2half2_rn(v1.x, v1.y);
            __half2 p3 = __floats2half2_rn(v1.z, v1.w);
            ob[q] = make_uint4(*(uint32_t*)&p0, *(uint32_t*)&p1,
                               *(uint32_t*)&p2, *(uint32_t*)&p3);
            *(uint4*)(e_s + f * FB_E_STRIDE + q * 8) = ob[q];
        }
        #pragma unroll
        for (int q = 0; q < 8; q++)
            *(uint4*)(h0 + base + f * EDIM + q * 8) = ob[q];
    }
    __syncwarp();

    {   // gram = e @ e^T via tensor cores (warp-local)
        const int la_row = lane & 15;
        const int la_col = (lane >> 4) << 3;
        const int lb_row = (lane & 7) + ((lane >> 4) << 3);
        const int lb_col = ((lane >> 3) & 1) << 3;

        float acc[2][4][4];
        #pragma unroll
        for (int mi = 0; mi < 2; mi++)
            #pragma unroll
            for (int nb = 0; nb < 4; nb++)
                #pragma unroll
                for (int q = 0; q < 4; q++) acc[mi][nb][q] = 0.f;

        #pragma unroll
        for (int ks = 0; ks < EDIM; ks += 16) {
            uint32_t ar[2][4], br[2][4];
            #pragma unroll
            for (int mi = 0; mi < 2; mi++) {
                const uint32_t off = (uint32_t)(((mi * 16 + la_row) * FB_E_STRIDE
                                                 + ks + la_col) * 2);
                ldsm4(smem_u32(e_s) + off, ar[mi][0], ar[mi][1], ar[mi][2], ar[mi][3]);
            }
            #pragma unroll
            for (int np = 0; np < 2; np++) {
                const uint32_t off = (uint32_t)(((np * 16 + lb_row) * FB_E_STRIDE
                                                 + ks + lb_col) * 2);
                ldsm4(smem_u32(e_s) + off, br[np][0], br[np][1], br[np][2], br[np][3]);
            }
            #pragma unroll
            for (int mi = 0; mi < 2; mi++)
                #pragma unroll
                for (int nb = 0; nb < 4; nb++)
                    mma_fp16(acc[mi][nb], ar[mi],
                             br[nb >> 1][(nb & 1) * 2],
                             br[nb >> 1][(nb & 1) * 2 + 1]);
        }

        #pragma unroll
        for (int mi = 0; mi < 2; mi++) {
            #pragma unroll
            for (int nb = 0; nb < 4; nb++) {
                const int r0 = mi * 16 + (lane >> 2);
                const int c0 = nb * 8 + (lane & 3) * 2;
                *(__half2*)(gram_s + r0 * 36 + c0) =
                    __floats2half2_rn(acc[mi][nb][0], acc[mi][nb][1]);
                *(__half2*)(gram_s + (r0 + 8) * 36 + c0) =
                    __floats2half2_rn(acc[mi][nb][2], acc[mi][nb][3]);
            }
        }
    }
    __syncwarp();

    for (int p = lane; p < NPAIR; p += 32) {
        const int pr = pairs_s[p];
        h0[base + NFEAT * EDIM + p] = gram_s[(pr >> 8) * 36 + (pr & 255)];
    }
    if (lane < K1P - DIN) h0[base + DIN + lane] = __float2half(0.f);
}

// ---------------------------------------------------------------------------
// fp16 tensor-core GEMM (unchanged from measured-best R9):
// C[M,N] = act( A @ B^T + bias ), fp32 accumulate
// BM=256, BN=64, BK=64; 256 threads, warps 4(m) x 2(n), warp tile 64x32.
// 2-stage cp.async ring; 2 CTAs/SM.
// ---------------------------------------------------------------------------
#define BM 256
#define BN 64
#define BKC 64
#define SPAD 72                           // halfs per row = 144B (16B-aligned)
#define A_BYTES (BM * SPAD * 2)           // 36864
#define B_BYTES (BN * SPAD * 2)           // 9216
#define STAGE_BYTES (A_BYTES + B_BYTES)   // 46080
#define SMEM_TOTAL (2 * STAGE_BYTES)      // 92160

template<int ACT>
__global__ __launch_bounds__(256, 2)
void mma_gemm_kernel(const f16* __restrict__ A, const f16* __restrict__ B,
                     const float* __restrict__ bias,
                     f16* __restrict__ Ch, float* __restrict__ Cf,
                     int Kp, int ldc, int nchunk) {
    extern __shared__ __align__(16) char smem[];

    const int tid  = threadIdx.x;
    const int lane = tid & 31;
    const int wid  = tid >> 5;
    const int wm   = (wid >> 1) * 64;
    const int wn   = (wid & 1) * 32;
    const int row0 = blockIdx.y * BM;
    const int col0 = blockIdx.x * BN;

    const int la_row = lane & 15;
    const int la_col = (lane >> 4) << 3;
    const int lb_row = (lane & 7) + ((lane >> 4) << 3);
    const int lb_col = ((lane >> 3) & 1) << 3;

    float acc[4][4][4];
    #pragma unroll
    for (int mi = 0; mi < 4; mi++)
        #pragma unroll
        for (int nb = 0; nb < 4; nb++)
            #pragma unroll
            for (int q = 0; q < 4; q++) acc[mi][nb][q] = 0.f;

    auto load_stage = [&](int s, int kc) {
        char* st = smem + s * STAGE_BYTES;
        const int k0 = kc * BKC;
        #pragma unroll
        for (int p = 0; p < 8; p++) {          // A: 256 rows x 8 segs
            const int c = tid + p * 256;
            const int r = c >> 3, sg = c & 7;
            const uint32_t so = (uint32_t)(r * (SPAD * 2) + sg * 16);
            const size_t g = (size_t)(row0 + r) * Kp + k0 + sg * 8;
            cp_async16(smem_u32(st + so), A + g);
        }
        #pragma unroll
        for (int p = 0; p < 2; p++) {          // B: 64 rows x 8 segs
            const int c = tid + p * 256;
            const int r = c >> 3, sg = c & 7;
            const uint32_t so = (uint32_t)(r * (SPAD * 2) + sg * 16);
            const size_t g = (size_t)(col0 + r) * Kp + k0 + sg * 8;
            cp_async16(smem_u32(st + A_BYTES + so), B + g);
        }
        asm volatile("cp.async.commit_group;\n" ::: "memory");
    };

    load_stage(0, 0);
    load_stage(1, 1);

    for (int i = 0; i < nchunk; i++) {
        if (i + 1 < nchunk) asm volatile("cp.async.wait_group 1;\n" ::: "memory");
        else                asm volatile("cp.async.wait_group 0;\n" ::: "memory");
        __syncthreads();

        const char* st = smem + (i & 1) * STAGE_BYTES;
        const uint32_t sA = smem_u32(st);
        const uint32_t sB = sA + A_BYTES;

        #pragma unroll
        for (int ks = 0; ks < BKC; ks += 16) {
            uint32_t ar[4][4], br[2][4];
            #pragma unroll
            for (int mi = 0; mi < 4; mi++) {
                const uint32_t off =
                    (uint32_t)(((wm + mi * 16 + la_row) * SPAD + ks + la_col) * 2);
                ldsm4(sA + off, ar[mi][0], ar[mi][1], ar[mi][2], ar[mi][3]);
            }
            #pragma unroll
            for (int np = 0; np < 2; np++) {
                const uint32_t off =
                    (uint32_t)(((wn + np * 16 + lb_row) * SPAD + ks + lb_col) * 2);
                ldsm4(sB + off, br[np][0], br[np][1], br[np][2], br[np][3]);
            }
            #pragma unroll
            for (int mi = 0; mi < 4; mi++) {
                #pragma unroll
                for (int nb = 0; nb < 4; nb++) {
                    mma_fp16(acc[mi][nb], ar[mi],
                             br[nb >> 1][(nb & 1) * 2],
                             br[nb >> 1][(nb & 1) * 2 + 1]);
                }
            }
        }
        __syncthreads();
        if (i + 2 < nchunk) load_stage(i & 1, i + 2);
    }

    // -------- epilogue --------
    #pragma unroll
    for (int mi = 0; mi < 4; mi++) {
        #pragma unroll
        for (int nb = 0; nb < 4; nb++) {
            const int rg = row0 + wm + mi * 16 + (lane >> 2);
            const int cg = col0 + wn + nb * 8 + (lane & 3) * 2;
            float b0 = 0.f, b1 = 0.f;
            if (ACT == 2) {
                if (cg < DOUT)     b0 = bias[cg];
                if (cg + 1 < DOUT) b1 = bias[cg + 1];
            } else {
                b0 = bias[cg];
                b1 = bias[cg + 1];
            }
            const float* a = acc[mi][nb];
            #pragma unroll
            for (int h = 0; h < 2; h++) {
                const int r = rg + h * 8;
                float v0 = a[h * 2 + 0] + b0;
                float v1 = a[h * 2 + 1] + b1;
                if (ACT == 1) {
                    v0 = fmaxf(v0, 0.f);
                    v1 = fmaxf(v1, 0.f);
                    *(__half2*)(Ch + (size_t)r * ldc + cg) = __floats2half2_rn(v0, v1);
                } else {
                    if (cg + 2 <= DOUT) {
                        float2 o;
                        o.x = 1.f / (1.f + __expf(-v0));
                        o.y = 1.f / (1.f + __expf(-v1));
                        *(float2*)(Cf + (size_t)r * DOUT + cg) = o;
                    }
                }
            }
        }
    }
}

// ---------------------------------------------------------------------------
extern "C" void kernel_launch(void* const* d_in, const int* in_sizes, int n_in,
                              void* d_out, int out_size) {
    const int*   x   = (const int*)  d_in[0];
    const float* emb = (const float*)d_in[1];
    const float* W1  = (const float*)d_in[2];
    const float* b1  = (const float*)d_in[3];
    const float* W2  = (const float*)d_in[4];
    const float* b2  = (const float*)d_in[5];
    const float* W3  = (const float*)d_in[6];
    const float* b3  = (const float*)d_in[7];
    float* out = (float*)d_out;

    f16 *h0, *h1, *h2, *w1, *w2, *w3;
    cudaGetSymbolAddress((void**)&h0, g_h0);
    cudaGetSymbolAddress((void**)&h1, g_h1);
    cudaGetSymbolAddress((void**)&h2, g_h2);
    cudaGetSymbolAddress((void**)&w1, g_W1);
    cudaGetSymbolAddress((void**)&w2, g_W2);
    cudaGetSymbolAddress((void**)&w3, g_W3);

    cudaFuncSetAttribute((const void*)prep_kernel,
                         cudaFuncAttributeMaxDynamicSharedMemorySize, PREP_SMEM);
    cudaFuncSetAttribute((const void*)mma_gemm_kernel<1>,
                         cudaFuncAttributeMaxDynamicSharedMemorySize, SMEM_TOTAL);
    cudaFuncSetAttribute((const void*)mma_gemm_kernel<2>,
                         cudaFuncAttributeMaxDynamicSharedMemorySize, SMEM_TOTAL);

    prep_kernel<<<PREP_BLKS, 256, PREP_SMEM>>>(x, emb, W1, W2, W3, w1, w2, w3, h0);

    mma_gemm_kernel<1><<<dim3(DH1 / BN, BATCH / BM), 256, SMEM_TOTAL>>>(
        h0, w1, b1, h1, nullptr, K1P, DH1, K1P / BKC);
    mma_gemm_kernel<1><<<dim3(DH2 / BN, BATCH / BM), 256, SMEM_TOTAL>>>(
        h1, w2, b2, h2, nullptr, DH1, DH2, DH1 / BKC);
    mma_gemm_kernel<2><<<dim3(N3P / BN, BATCH / BM), 256, SMEM_TOTAL>>>(
        h2, w3, b3, nullptr, out, DH2, 0, DH2 / BKC);
}